// round 12
// baseline (speedup 1.0000x reference)
#include <cuda_runtime.h>
#include <cuda_fp16.h>
#include <cstdint>
#include <cstddef>

// Problem constants
#define LSEQ 2048
#define EDIM 512
#define HEADS 8
#define DDIM 64
#define E3   1536
#define CHUNK 64
#define NCH  32

#define THETA_SCALE 7.66990393942820573e-4f  // (pi/2)/2048

// ---------------- scratch (device globals; no allocs allowed) ----------------
__device__ float g_qkv[LSEQ * E3];
__device__ float g_ckv[HEADS * NCH * 2 * DDIM * DDIM];
__device__ float g_ck [HEADS * NCH * 2 * DDIM];
__device__ float g_pkv[HEADS * NCH * 2 * DDIM * DDIM];
__device__ float g_pk [HEADS * NCH * 2 * DDIM];

// fp16 split buffers (fp16x2 scheme: A = Ah + Al, B = Bh only)
__device__ __half g_xh[LSEQ * EDIM];
__device__ __half g_xl[LSEQ * EDIM];
__device__ __half g_wqh[E3 * EDIM];   // Wqkv^T  [1536][512]
__device__ __half g_woh[EDIM * EDIM]; // Wout^T  [512][512]
__device__ __half g_ah[LSEQ * EDIM];  // attention out hi/lo
__device__ __half g_al[LSEQ * EDIM];

// ---------------- low-level helpers ----------------
__device__ __forceinline__ uint32_t smem_u32(const void* p) {
    uint32_t a;
    asm("{ .reg .u64 t; cvta.to.shared.u64 t, %1; cvt.u32.u64 %0, t; }"
        : "=r"(a) : "l"(p));
    return a;
}
#define CP_ASYNC16(dst, src) \
    asm volatile("cp.async.cg.shared.global [%0], [%1], 16;" :: "r"(dst), "l"(src))
#define CP_COMMIT() asm volatile("cp.async.commit_group;" ::: "memory")
#define CP_WAIT0()  asm volatile("cp.async.wait_group 0;" ::: "memory")
#define CP_WAIT1()  asm volatile("cp.async.wait_group 1;" ::: "memory")
#define CP_WAIT2()  asm volatile("cp.async.wait_group 2;" ::: "memory")

__device__ __forceinline__ void ldmx4(uint32_t* r, uint32_t addr) {
    asm volatile("ldmatrix.sync.aligned.m8n8.x4.shared.b16 {%0,%1,%2,%3}, [%4];"
                 : "=r"(r[0]), "=r"(r[1]), "=r"(r[2]), "=r"(r[3]) : "r"(addr));
}
__device__ __forceinline__ void mma16816(float* c, const uint32_t* a, const uint32_t* b) {
    asm volatile(
        "mma.sync.aligned.m16n8k16.row.col.f32.f16.f16.f32 "
        "{%0,%1,%2,%3}, {%4,%5,%6,%7}, {%8,%9}, {%0,%1,%2,%3};"
        : "+f"(c[0]), "+f"(c[1]), "+f"(c[2]), "+f"(c[3])
        : "r"(a[0]), "r"(a[1]), "r"(a[2]), "r"(a[3]), "r"(b[0]), "r"(b[1]));
}

// ---------------- fused split kernel: x hi/lo + both weight transposes ------
__device__ __forceinline__ void transpose_split_tile(
    const float* __restrict__ W, __half* __restrict__ hiT,
    int K, int N, int bx, int by, float (*t)[33]) {
    const int tx = threadIdx.x & 31, ty = threadIdx.x >> 5;  // (32, 8)
    const int n0 = bx * 32, k0 = by * 32;
    #pragma unroll
    for (int j = 0; j < 4; j++)
        t[ty + 8 * j][tx] = W[(size_t)(k0 + ty + 8 * j) * N + n0 + tx];
    __syncthreads();
    #pragma unroll
    for (int j = 0; j < 4; j++)
        hiT[(size_t)(n0 + ty + 8 * j) * K + k0 + tx] = __float2half(t[tx][ty + 8 * j]);
}

__global__ __launch_bounds__(256)
void split_all_kernel(const float* __restrict__ x,
                      const float* __restrict__ Wqkv,
                      const float* __restrict__ Wout) {
    __shared__ float t[32][33];
    const int b = blockIdx.x;
    if (b < 1024) {
        int i = b * 1024 + threadIdx.x * 4;
        float4 a4 = *reinterpret_cast<const float4*>(&x[i]);
        float av[4] = {a4.x, a4.y, a4.z, a4.w};
        __half hv[4], lv[4];
        #pragma unroll
        for (int k = 0; k < 4; k++) {
            hv[k] = __float2half(av[k]);
            lv[k] = __float2half(av[k] - __half2float(hv[k]));
        }
        *reinterpret_cast<uint2*>(&g_xh[i]) = *reinterpret_cast<uint2*>(hv);
        *reinterpret_cast<uint2*>(&g_xl[i]) = *reinterpret_cast<uint2*>(lv);
    } else if (b < 1024 + 768) {
        int tt = b - 1024;                 // Wqkv: K=512, N=1536 -> 48 x 16 tiles
        transpose_split_tile(Wqkv, g_wqh, EDIM, E3, tt % 48, tt / 48, t);
    } else {
        int tt = b - 1024 - 768;           // Wout: K=512, N=512 -> 16 x 16 tiles
        transpose_split_tile(Wout, g_woh, EDIM, EDIM, tt % 16, tt / 16, t);
    }
}

// ---------------- mma.sync fp16x2 GEMM: C[M,N] = A @ Bt^T + bias --------------
// A = Ah + Al (fp16 hi/lo), B = Bh (single fp16). 2 MMAs per tile.
// BN = 128 fixed. 8 warps as 2(M) x 4(N): warp tile (BM/2) x 32.
// K-chunk 32, 3-stage cp.async pipeline, 3 CTAs/SM. K templated -> full unroll.
#define KC 32
#define AST 40   // smem row stride in fp16 elems

template<int BM, int KT>
__global__ __launch_bounds__(256, 3)
void mma_gemm_kernel(const __half* __restrict__ Ah, const __half* __restrict__ Al,
                     const __half* __restrict__ Bh,
                     const float* __restrict__ bias, float* __restrict__ C,
                     int N) {
    constexpr int MI = BM / 32;
    constexpr int TILE_A = BM * AST;
    constexpr int TILE_B = 128 * AST;
    constexpr int BUF_E  = 2 * TILE_A + TILE_B;
    constexpr int NCHK   = KT / KC;   // 16

    extern __shared__ __half smem[];
    const int tid = threadIdx.x;
    const int wid = tid >> 5, lane = tid & 31;
    const int bn0 = blockIdx.x * 128, bm0 = blockIdx.y * BM;
    const int wm = (wid & 1) * (BM / 2);
    const int wn = (wid >> 1) * 32;

    const uint32_t smb = smem_u32(smem);

    float acc[MI][4][4];
    #pragma unroll
    for (int mi = 0; mi < MI; mi++)
        #pragma unroll
        for (int nj = 0; nj < 4; nj++)
            #pragma unroll
            for (int r = 0; r < 4; r++) acc[mi][nj][r] = 0.f;

    const __half* srcs[3] = {Ah, Al, Bh};
    const int  srow[3] = {bm0, bm0, bn0};
    const int  titem[3] = {BM * KC / 8, BM * KC / 8, 128 * KC / 8};
    const uint32_t toff[3] = {0u, (uint32_t)TILE_A, (uint32_t)(2 * TILE_A)};

    auto load_chunk = [&](int b, int k0) {
        #pragma unroll
        for (int t = 0; t < 3; t++) {
            const __half* s = srcs[t];
            uint32_t dbase = smb + (uint32_t)(b * BUF_E + toff[t]) * 2u;
            const int nit = titem[t];
            #pragma unroll
            for (int item0 = 0; item0 < 512; item0 += 256) {
                int item = item0 + tid;
                if (item < nit) {                 // per-thread guard (bounds-safe)
                    int row = item >> 2, sub = item & 3;
                    uint32_t d = dbase + (uint32_t)(row * AST + sub * 8) * 2u;
                    const void* g = (const void*)(s + (size_t)(srow[t] + row) * KT + k0 + sub * 8);
                    CP_ASYNC16(d, g);
                }
            }
        }
        CP_COMMIT();
    };

    load_chunk(0, 0);
    load_chunk(1, KC);

    #pragma unroll
    for (int c = 0; c < NCHK; c++) {
        const int b = c % 3;
        if (c + 2 < NCHK) load_chunk((c + 2) % 3, (c + 2) * KC);
        if (c + 2 < NCHK)      CP_WAIT2();
        else if (c + 1 < NCHK) CP_WAIT1();
        else                   CP_WAIT0();
        __syncthreads();

        const uint32_t aBh = smb + (uint32_t)(b * BUF_E) * 2u;
        const uint32_t aBl = aBh + (uint32_t)TILE_A * 2u;
        const uint32_t bBh = aBh + (uint32_t)(2 * TILE_A) * 2u;

        #pragma unroll
        for (int ks = 0; ks < KC; ks += 16) {
            const int arow = wm + (lane & 15);
            const int acol = ks + ((lane >> 4) << 3);
            uint32_t ah[MI][4], al[MI][4];
            #pragma unroll
            for (int mi = 0; mi < MI; mi++) {
                uint32_t off = (uint32_t)((arow + mi * 16) * AST + acol) * 2u;
                ldmx4(ah[mi], aBh + off);
                ldmx4(al[mi], aBl + off);
            }
            const int brow = wn + (lane & 7) + ((lane & 16) ? 8 : 0);
            const int bcol = ks + ((lane & 8) ? 8 : 0);
            uint32_t bh[2][4];
            #pragma unroll
            for (int ni = 0; ni < 2; ni++) {
                uint32_t off = (uint32_t)((brow + ni * 16) * AST + bcol) * 2u;
                ldmx4(bh[ni], bBh + off);
            }
            #pragma unroll
            for (int mi = 0; mi < MI; mi++) {
                #pragma unroll
                for (int nj = 0; nj < 4; nj++) {
                    const uint32_t* ph = &bh[nj >> 1][(nj & 1) * 2];
                    mma16816(acc[mi][nj], ah[mi], ph);
                    mma16816(acc[mi][nj], al[mi], ph);
                }
            }
        }
        __syncthreads();
    }

    const int r0 = bm0 + wm + (lane >> 2);
    const int c0 = bn0 + wn + (lane & 3) * 2;
    #pragma unroll
    for (int mi = 0; mi < MI; mi++) {
        #pragma unroll
        for (int nj = 0; nj < 4; nj++) {
            int row = r0 + mi * 16;
            int col = c0 + nj * 8;
            float b0 = bias[col], b1 = bias[col + 1];
            float2 v0 = make_float2(acc[mi][nj][0] + b0, acc[mi][nj][1] + b1);
            float2 v1 = make_float2(acc[mi][nj][2] + b0, acc[mi][nj][3] + b1);
            *reinterpret_cast<float2*>(&C[(size_t)row * N + col]) = v0;
            *reinterpret_cast<float2*>(&C[(size_t)(row + 8) * N + col]) = v1;
        }
    }
}

// smem bytes: 3 buffers x (2*BM + 128) * AST * 2 bytes
#define GSMEM(BM) ((2 * BM + 128) * AST * 6)

// ---------------------------------------------------------------------------
// chunk_sum: per-chunk (C=64) KV / K sums. grid (NCH, HEADS) = 256 blocks.
// Thread map: d = tid>>2, eg = (tid&3)*16  -> coalesced float4 stores.
// ---------------------------------------------------------------------------
__global__ __launch_bounds__(256)
void chunk_sum_kernel() {
    extern __shared__ float smf[];
    float* rk = smf;                 // [64][64]
    float* vv = rk + CHUNK * DDIM;   // [64][64]
    float* cw = vv + CHUNK * DDIM;   // [64]
    float* sw = cw + CHUNK;          // [64]

    const int c = blockIdx.x, h = blockIdx.y, tid = threadIdx.x;

    for (int t = tid; t < CHUNK * DDIM; t += 256) {
        int i = t >> 6, d = t & 63;
        const float* row = g_qkv + (size_t)(c * CHUNK + i) * E3 + h * DDIM;
        rk[t] = fmaxf(row[EDIM + d], 0.f);
        vv[t] = row[2 * EDIM + d];
    }
    if (tid < CHUNK) {
        float th = (float)(c * CHUNK + tid) * THETA_SCALE;
        cw[tid] = cosf(th);
        sw[tid] = sinf(th);
    }
    __syncthreads();

    const int d  = tid >> 2;          // 0..63
    const int eg = (tid & 3) << 4;    // 0,16,32,48
    float aC[16], aS[16];
    #pragma unroll
    for (int e = 0; e < 16; e++) { aC[e] = 0.f; aS[e] = 0.f; }

    for (int i = 0; i < CHUNK; i++) {
        float kd = rk[i * DDIM + d];
        float kc = kd * cw[i];
        float ks = kd * sw[i];
        const float4* vp = reinterpret_cast<const float4*>(&vv[i * DDIM + eg]);
        #pragma unroll
        for (int e4 = 0; e4 < 4; e4++) {
            float4 v4 = vp[e4];
            aC[e4 * 4 + 0] += kc * v4.x; aC[e4 * 4 + 1] += kc * v4.y;
            aC[e4 * 4 + 2] += kc * v4.z; aC[e4 * 4 + 3] += kc * v4.w;
            aS[e4 * 4 + 0] += ks * v4.x; aS[e4 * 4 + 1] += ks * v4.y;
            aS[e4 * 4 + 2] += ks * v4.z; aS[e4 * 4 + 3] += ks * v4.w;
        }
    }

    size_t base = (size_t)(h * NCH + c) * 2 * DDIM * DDIM;
    float4* pc = reinterpret_cast<float4*>(&g_ckv[base + d * DDIM + eg]);
    float4* ps = reinterpret_cast<float4*>(&g_ckv[base + DDIM * DDIM + d * DDIM + eg]);
    #pragma unroll
    for (int e4 = 0; e4 < 4; e4++) {
        pc[e4] = make_float4(aC[e4 * 4 + 0], aC[e4 * 4 + 1], aC[e4 * 4 + 2], aC[e4 * 4 + 3]);
        ps[e4] = make_float4(aS[e4 * 4 + 0], aS[e4 * 4 + 1], aS[e4 * 4 + 2], aS[e4 * 4 + 3]);
    }

    if (tid < DDIM) {
        float sc = 0.f, ss = 0.f;
        for (int i = 0; i < CHUNK; i++) {
            float kd = rk[i * DDIM + tid];
            sc += kd * cw[i];
            ss += kd * sw[i];
        }
        size_t kb = (size_t)(h * NCH + c) * 2 * DDIM;
        g_ck[kb + tid]        = sc;
        g_ck[kb + DDIM + tid] = ss;
    }
}

// ---------------------------------------------------------------------------
// scan: exclusive prefix over 32 chunks, float4-vectorized.
// grid 64 blocks (8 per head) x 256 threads, one thread per 4 lanes.
// ---------------------------------------------------------------------------
__global__ __launch_bounds__(256)
void scan_kernel() {
    const int h = blockIdx.x >> 3;
    const int q = (blockIdx.x & 7) * 256 + threadIdx.x;  // float4 lane 0..2047
    const int KV4 = 2 * DDIM * DDIM / 4;                 // 2048

    const float4* src = reinterpret_cast<const float4*>(g_ckv);
    float4* dst = reinterpret_cast<float4*>(g_pkv);

    float4 v[NCH];
    #pragma unroll
    for (int c = 0; c < NCH; c++)
        v[c] = src[(size_t)(h * NCH + c) * KV4 + q];
    float4 run = make_float4(0.f, 0.f, 0.f, 0.f);
    #pragma unroll
    for (int c = 0; c < NCH; c++) {
        dst[(size_t)(h * NCH + c) * KV4 + q] = run;
        run.x += v[c].x; run.y += v[c].y; run.z += v[c].z; run.w += v[c].w;
    }

    if ((blockIdx.x & 7) == 0 && threadIdx.x < 2 * DDIM) {
        const int t = threadIdx.x;
        const int KSZ = 2 * DDIM;
        float w[NCH];
        #pragma unroll
        for (int c = 0; c < NCH; c++)
            w[c] = g_ck[(size_t)(h * NCH + c) * KSZ + t];
        float r2 = 0.f;
        #pragma unroll
        for (int c = 0; c < NCH; c++) {
            g_pk[(size_t)(h * NCH + c) * KSZ + t] = r2;
            r2 += w[c];
        }
    }
}

// ---------------------------------------------------------------------------
// chunk_out (C=64): register-tiled, predicated-causal, fused fp16-split out.
// grid (NCH, HEADS) = 256 blocks, 256 threads.
// ---------------------------------------------------------------------------
#define RQT_STRIDE 68
#define S_STRIDE   66

__global__ __launch_bounds__(256)
void chunk_out_kernel() {
    extern __shared__ float smf[];
    float* rqT = smf;                       // [64][68]
    float* rkT = rqT + DDIM * RQT_STRIDE;   // [64][68]
    float* vv  = rkT + DDIM * RQT_STRIDE;   // [64][64]
    float* S   = vv + CHUNK * DDIM;         // [64][66]
    float* KVc = S + CHUNK * S_STRIDE;      // [64][64]
    float* KVs = KVc + DDIM * DDIM;         // [64][64]
    float* K0c = KVs + DDIM * DDIM;         // [64]
    float* K0s = K0c + DDIM;                // [64]
    float* cw  = K0s + DDIM;                // [64]
    float* sw  = cw + CHUNK;                // [64]
    float* nrm = sw + CHUNK;                // [64]

    const int c = blockIdx.x, h = blockIdx.y, tid = threadIdx.x;

    for (int t = tid; t < CHUNK * DDIM; t += 256) {
        int i = t >> 6, d = t & 63;
        const float* row = g_qkv + (size_t)(c * CHUNK + i) * E3 + h * DDIM;
        rqT[d * RQT_STRIDE + i] = fmaxf(row[d], 0.f);
        rkT[d * RQT_STRIDE + i] = fmaxf(row[EDIM + d], 0.f);
        vv[i * DDIM + d]        = row[2 * EDIM + d];
    }
    if (tid < CHUNK) {
        float th = (float)(c * CHUNK + tid) * THETA_SCALE;
        cw[tid] = cosf(th);
        sw[tid] = sinf(th);
    }
    {
        const float* base = g_pkv + (size_t)(h * NCH + c) * 2 * DDIM * DDIM;
        for (int t = tid; t < 2 * DDIM * DDIM; t += 256) {
            if (t < DDIM * DDIM) KVc[t] = base[t];
            else                 KVs[t - DDIM * DDIM] = base[t];
        }
        const float* kb = g_pk + (size_t)(h * NCH + c) * 2 * DDIM;
        if (tid < 2 * DDIM) {
            if (tid < DDIM) K0c[tid] = kb[tid];
            else            K0s[tid - DDIM] = kb[tid];
        }
    }
    __syncthreads();

    // ---- phase 1: S[i][j] (j<=i), 4x4 tiles on a 16x16 thread grid
    {
        const int ti = tid >> 4, tj = tid & 15;
        const int i0 = ti * 4, j0 = tj * 4;
        if (j0 <= i0 + 3) {
            float acc[4][4];
            #pragma unroll
            for (int r = 0; r < 4; r++)
                #pragma unroll
                for (int q = 0; q < 4; q++) acc[r][q] = 0.f;

            for (int d = 0; d < DDIM; d++) {
                float4 a4 = *reinterpret_cast<const float4*>(&rqT[d * RQT_STRIDE + i0]);
                float4 b4 = *reinterpret_cast<const float4*>(&rkT[d * RQT_STRIDE + j0]);
                float a[4] = {a4.x, a4.y, a4.z, a4.w};
                float b[4] = {b4.x, b4.y, b4.z, b4.w};
                #pragma unroll
                for (int r = 0; r < 4; r++)
                    #pragma unroll
                    for (int q = 0; q < 4; q++)
                        acc[r][q] += a[r] * b[q];
            }
            #pragma unroll
            for (int r = 0; r < 4; r++) {
                int i = i0 + r;
                float ci = cw[i], si = sw[i];
                #pragma unroll
                for (int q = 0; q < 4; q++) {
                    int j = j0 + q;
                    if (j <= i)
                        S[i * S_STRIDE + j] = acc[r][q] * (ci * cw[j] + si * sw[j]);
                }
            }
        }
    }
    __syncthreads();

    // ---- phase 2: nrm
    if (tid < CHUNK) {
        const int i = tid;
        float dc = 0.f, ds = 0.f;
        for (int d = 0; d < DDIM; d++) {
            float q = rqT[d * RQT_STRIDE + i];
            dc += q * K0c[d];
            ds += q * K0s[d];
        }
        float n = cw[i] * dc + sw[i] * ds;
        for (int j = 0; j <= i; j++) n += S[i * S_STRIDE + j];
        nrm[i] = n;
    }
    __syncthreads();

    // ---- phase 3: 2 rows x 8 cols per thread
    const int tx = tid & 7, ty = tid >> 3;
    const int e0 = tx * 8, i0 = ty * 2;

    float tC[2][8], tS[2][8], tI[2][8];
    #pragma unroll
    for (int r = 0; r < 2; r++)
        #pragma unroll
        for (int e = 0; e < 8; e++) { tC[r][e] = 0.f; tS[r][e] = 0.f; tI[r][e] = 0.f; }

    for (int d = 0; d < DDIM; d++) {
        float2 q2 = *reinterpret_cast<const float2*>(&rqT[d * RQT_STRIDE + i0]);
        float qr[2] = {q2.x, q2.y};
        float4 c0 = *reinterpret_cast<const float4*>(&KVc[d * DDIM + e0]);
        float4 c1 = *reinterpret_cast<const float4*>(&KVc[d * DDIM + e0 + 4]);
        float4 s0 = *reinterpret_cast<const float4*>(&KVs[d * DDIM + e0]);
        float4 s1 = *reinterpret_cast<const float4*>(&KVs[d * DDIM + e0 + 4]);
        float cv[8] = {c0.x, c0.y, c0.z, c0.w, c1.x, c1.y, c1.z, c1.w};
        float sv[8] = {s0.x, s0.y, s0.z, s0.w, s1.x, s1.y, s1.z, s1.w};
        #pragma unroll
        for (int r = 0; r < 2; r++)
            #pragma unroll
            for (int e = 0; e < 8; e++) {
                tC[r][e] += qr[r] * cv[e];
                tS[r][e] += qr[r] * sv[e];
            }
    }

    for (int j = 0; j <= i0; j++) {
        float sr[2];
        #pragma unroll
        for (int r = 0; r < 2; r++) sr[r] = S[(i0 + r) * S_STRIDE + j];
        float4 v0 = *reinterpret_cast<const float4*>(&vv[j * DDIM + e0]);
        float4 v1 = *reinterpret_cast<const float4*>(&vv[j * DDIM + e0 + 4]);
        float ve[8] = {v0.x, v0.y, v0.z, v0.w, v1.x, v1.y, v1.z, v1.w};
        #pragma unroll
        for (int r = 0; r < 2; r++)
            #pragma unroll
            for (int e = 0; e < 8; e++)
                tI[r][e] += sr[r] * ve[e];
    }
    {   // tail j = i0+1, valid only for r=1
        const int j = i0 + 1;
        float s1 = S[(i0 + 1) * S_STRIDE + j];
        float4 v0 = *reinterpret_cast<const float4*>(&vv[j * DDIM + e0]);
        float4 v1 = *reinterpret_cast<const float4*>(&vv[j * DDIM + e0 + 4]);
        float ve[8] = {v0.x, v0.y, v0.z, v0.w, v1.x, v1.y, v1.z, v1.w};
        #pragma unroll
        for (int e = 0; e < 8; e++)
            tI[1][e] += s1 * ve[e];
    }

    // ---- epilogue: combine, normalize, fp16 hi/lo split, store
    #pragma unroll
    for (int r = 0; r < 2; r++) {
        const int i = i0 + r;
        float ci = cw[i], si = sw[i];
        float inv = 1.0f / (nrm[i] + 1e-6f);
        uint32_t ph[4], pl[4];
        #pragma unroll
        for (int e2 = 0; e2 < 4; e2++) {
            float v0 = (ci * tC[r][e2 * 2 + 0] + si * tS[r][e2 * 2 + 0] + tI[r][e2 * 2 + 0]) * inv;
            float v1 = (ci * tC[r][e2 * 2 + 1] + si * tS[r][e2 * 2 + 1] + tI[r][e2 * 2 + 1]) * inv;
            __half h0 = __float2half(v0);
            __half h1 = __float2half(v1);
            __half l0 = __float2half(v0 - __half2float(h0));
            __half l1 = __float2half(v1 - __half2float(h1));
            ph[e2] = (uint32_t)__half_as_ushort(h0) |
                     ((uint32_t)__half_as_ushort(h1) << 16);
            pl[e2] = (uint32_t)__half_as_ushort(l0) |
                     ((uint32_t)__half_as_ushort(l1) << 16);
        }
        size_t base = (size_t)(c * CHUNK + i) * EDIM + h * DDIM + e0;
        *reinterpret_cast<uint4*>(&g_ah[base]) = make_uint4(ph[0], ph[1], ph[2], ph[3]);
        *reinterpret_cast<uint4*>(&g_al[base]) = make_uint4(pl[0], pl[1], pl[2], pl[3]);
    }
}

// ---------------------------------------------------------------------------

static const int SMEM_SUM = (2 * CHUNK * DDIM + 2 * CHUNK) * (int)sizeof(float);
static const int SMEM_OUT = (2 * DDIM * RQT_STRIDE + CHUNK * DDIM + CHUNK * S_STRIDE +
                             2 * DDIM * DDIM + 2 * DDIM + 3 * CHUNK) * (int)sizeof(float);

extern "C" void kernel_launch(void* const* d_in, const int* in_sizes, int n_in,
                              void* d_out, int out_size) {
    (void)in_sizes; (void)n_in; (void)out_size;
    const float* x    = (const float*)d_in[0];
    const float* Wqkv = (const float*)d_in[1];
    const float* bqkv = (const float*)d_in[2];
    const float* Wout = (const float*)d_in[3];
    const float* bout = (const float*)d_in[4];
    float* out = (float*)d_out;

    float* qkv_ptr;
    cudaGetSymbolAddress((void**)&qkv_ptr, g_qkv);
    __half *xh, *xl, *wqh, *woh, *ah, *al;
    cudaGetSymbolAddress((void**)&xh, g_xh);
    cudaGetSymbolAddress((void**)&xl, g_xl);
    cudaGetSymbolAddress((void**)&wqh, g_wqh);
    cudaGetSymbolAddress((void**)&woh, g_woh);
    cudaGetSymbolAddress((void**)&ah, g_ah);
    cudaGetSymbolAddress((void**)&al, g_al);

    cudaFuncSetAttribute(chunk_sum_kernel,
                         cudaFuncAttributeMaxDynamicSharedMemorySize, SMEM_SUM);
    cudaFuncSetAttribute(chunk_out_kernel,
                         cudaFuncAttributeMaxDynamicSharedMemorySize, SMEM_OUT);
    cudaFuncSetAttribute((const void*)mma_gemm_kernel<64, EDIM>,
                         cudaFuncAttributeMaxDynamicSharedMemorySize, GSMEM(64));
    cudaFuncSetAttribute((const void*)mma_gemm_kernel<32, EDIM>,
                         cudaFuncAttributeMaxDynamicSharedMemorySize, GSMEM(32));

    // fused fp16 splits: x hi/lo + Wqkv^T hi + Wout^T hi, one launch
    split_all_kernel<<<1024 + 768 + 256, 256>>>(x, Wqkv, Wout);

    // 1) QKV GEMM: 64x128 tiles -> grid 384, 3 CTAs/SM, 3-stage, K unrolled
    mma_gemm_kernel<64, EDIM><<<dim3(E3 / 128, LSEQ / 64), 256, GSMEM(64)>>>(
        xh, xl, wqh, bqkv, qkv_ptr, E3);

    // 2) Chunked cosformer attention
    chunk_sum_kernel<<<dim3(NCH, HEADS), 256, SMEM_SUM>>>();
    scan_kernel<<<64, 256>>>();
    chunk_out_kernel<<<dim3(NCH, HEADS), 256, SMEM_OUT>>>();

    // 3) Output GEMM: 32x128 tiles -> grid 256
    mma_gemm_kernel<32, EDIM><<<dim3(EDIM / 128, LSEQ / 32), 256, GSMEM(32)>>>(
        ah, al, woh, bout, out, EDIM);
}

// round 13
// speedup vs baseline: 1.0006x; 1.0006x over previous
#include <cuda_runtime.h>
#include <cuda_fp16.h>
#include <cstdint>
#include <cstddef>

// Problem constants
#define LSEQ 2048
#define EDIM 512
#define HEADS 8
#define DDIM 64
#define E3   1536
#define CHUNK 64
#define NCH  32

#define THETA_SCALE 7.66990393942820573e-4f  // (pi/2)/2048

// ---------------- scratch (device globals; no allocs allowed) ----------------
__device__ float g_qkv[LSEQ * E3];
__device__ float g_ckv[HEADS * NCH * 2 * DDIM * DDIM];
__device__ float g_ck [HEADS * NCH * 2 * DDIM];
__device__ float g_pkv[HEADS * NCH * 2 * DDIM * DDIM];
__device__ float g_pk [HEADS * NCH * 2 * DDIM];

// fp16 split buffers (fp16x2 scheme: A = Ah + Al, B = Bh only)
__device__ __half g_xh[LSEQ * EDIM];
__device__ __half g_xl[LSEQ * EDIM];
__device__ __half g_wqh[E3 * EDIM];   // Wqkv^T  [1536][512]
__device__ __half g_woh[EDIM * EDIM]; // Wout^T  [512][512]
__device__ __half g_ah[LSEQ * EDIM];  // attention out hi/lo
__device__ __half g_al[LSEQ * EDIM];

// ---------------- low-level helpers ----------------
__device__ __forceinline__ uint32_t smem_u32(const void* p) {
    uint32_t a;
    asm("{ .reg .u64 t; cvta.to.shared.u64 t, %1; cvt.u32.u64 %0, t; }"
        : "=r"(a) : "l"(p));
    return a;
}
#define CP_ASYNC16(dst, src) \
    asm volatile("cp.async.cg.shared.global [%0], [%1], 16;" :: "r"(dst), "l"(src))
#define CP_COMMIT() asm volatile("cp.async.commit_group;" ::: "memory")
#define CP_WAIT0()  asm volatile("cp.async.wait_group 0;" ::: "memory")
#define CP_WAIT1()  asm volatile("cp.async.wait_group 1;" ::: "memory")
#define CP_WAIT2()  asm volatile("cp.async.wait_group 2;" ::: "memory")

__device__ __forceinline__ void ldmx4(uint32_t* r, uint32_t addr) {
    asm volatile("ldmatrix.sync.aligned.m8n8.x4.shared.b16 {%0,%1,%2,%3}, [%4];"
                 : "=r"(r[0]), "=r"(r[1]), "=r"(r[2]), "=r"(r[3]) : "r"(addr));
}
__device__ __forceinline__ void mma16816(float* c, const uint32_t* a, const uint32_t* b) {
    asm volatile(
        "mma.sync.aligned.m16n8k16.row.col.f32.f16.f16.f32 "
        "{%0,%1,%2,%3}, {%4,%5,%6,%7}, {%8,%9}, {%0,%1,%2,%3};"
        : "+f"(c[0]), "+f"(c[1]), "+f"(c[2]), "+f"(c[3])
        : "r"(a[0]), "r"(a[1]), "r"(a[2]), "r"(a[3]), "r"(b[0]), "r"(b[1]));
}

// ---------------- fused split kernel: x hi/lo + both weight transposes ------
__device__ __forceinline__ void transpose_split_tile(
    const float* __restrict__ W, __half* __restrict__ hiT,
    int K, int N, int bx, int by, float (*t)[33]) {
    const int tx = threadIdx.x & 31, ty = threadIdx.x >> 5;  // (32, 8)
    const int n0 = bx * 32, k0 = by * 32;
    #pragma unroll
    for (int j = 0; j < 4; j++)
        t[ty + 8 * j][tx] = W[(size_t)(k0 + ty + 8 * j) * N + n0 + tx];
    __syncthreads();
    #pragma unroll
    for (int j = 0; j < 4; j++)
        hiT[(size_t)(n0 + ty + 8 * j) * K + k0 + tx] = __float2half(t[tx][ty + 8 * j]);
}

__global__ __launch_bounds__(256)
void split_all_kernel(const float* __restrict__ x,
                      const float* __restrict__ Wqkv,
                      const float* __restrict__ Wout) {
    __shared__ float t[32][33];
    const int b = blockIdx.x;
    if (b < 1024) {
        int i = b * 1024 + threadIdx.x * 4;
        float4 a4 = *reinterpret_cast<const float4*>(&x[i]);
        float av[4] = {a4.x, a4.y, a4.z, a4.w};
        __half hv[4], lv[4];
        #pragma unroll
        for (int k = 0; k < 4; k++) {
            hv[k] = __float2half(av[k]);
            lv[k] = __float2half(av[k] - __half2float(hv[k]));
        }
        *reinterpret_cast<uint2*>(&g_xh[i]) = *reinterpret_cast<uint2*>(hv);
        *reinterpret_cast<uint2*>(&g_xl[i]) = *reinterpret_cast<uint2*>(lv);
    } else if (b < 1024 + 768) {
        int tt = b - 1024;                 // Wqkv: K=512, N=1536 -> 48 x 16 tiles
        transpose_split_tile(Wqkv, g_wqh, EDIM, E3, tt % 48, tt / 48, t);
    } else {
        int tt = b - 1024 - 768;           // Wout: K=512, N=512 -> 16 x 16 tiles
        transpose_split_tile(Wout, g_woh, EDIM, EDIM, tt % 16, tt / 16, t);
    }
}

// ---------------- mma.sync fp16x2 GEMM: C[M,N] = A @ Bt^T + bias --------------
// A = Ah + Al (fp16 hi/lo), B = Bh (single fp16). 2 MMAs per tile.
// BN = 128 fixed. 8 warps as 2(M) x 4(N): warp tile (BM/2) x 32.
// K-chunk 32, 3-stage cp.async pipeline, 3 CTAs/SM. (R10-proven form.)
#define KC 32
#define AST 40   // smem row stride in fp16 elems

template<int BM>
__global__ __launch_bounds__(256, 3)
void mma_gemm_kernel(const __half* __restrict__ Ah, const __half* __restrict__ Al,
                     const __half* __restrict__ Bh,
                     const float* __restrict__ bias, float* __restrict__ C,
                     int N, int K) {
    constexpr int MI = BM / 32;
    constexpr int TILE_A = BM * AST;
    constexpr int TILE_B = 128 * AST;
    constexpr int BUF_E  = 2 * TILE_A + TILE_B;

    extern __shared__ __half smem[];
    const int tid = threadIdx.x;
    const int wid = tid >> 5, lane = tid & 31;
    const int bn0 = blockIdx.x * 128, bm0 = blockIdx.y * BM;
    const int wm = (wid & 1) * (BM / 2);
    const int wn = (wid >> 1) * 32;

    const uint32_t smb = smem_u32(smem);
    const int NCHK = K / KC;

    float acc[MI][4][4];
    #pragma unroll
    for (int mi = 0; mi < MI; mi++)
        #pragma unroll
        for (int nj = 0; nj < 4; nj++)
            #pragma unroll
            for (int r = 0; r < 4; r++) acc[mi][nj][r] = 0.f;

    const __half* srcs[3] = {Ah, Al, Bh};
    const int  srow[3] = {bm0, bm0, bn0};
    const int  titem[3] = {BM * KC / 8, BM * KC / 8, 128 * KC / 8};
    const uint32_t toff[3] = {0u, (uint32_t)TILE_A, (uint32_t)(2 * TILE_A)};

    auto load_chunk = [&](int b, int k0) {
        #pragma unroll
        for (int t = 0; t < 3; t++) {
            const __half* s = srcs[t];
            uint32_t dbase = smb + (uint32_t)(b * BUF_E + toff[t]) * 2u;
            const int nit = titem[t];
            for (int item = tid; item < nit; item += 256) {
                int row = item >> 2, sub = item & 3;
                uint32_t d = dbase + (uint32_t)(row * AST + sub * 8) * 2u;
                const void* g = (const void*)(s + (size_t)(srow[t] + row) * K + k0 + sub * 8);
                CP_ASYNC16(d, g);
            }
        }
        CP_COMMIT();
    };

    load_chunk(0, 0);
    load_chunk(1, KC);

    for (int c = 0; c < NCHK; c++) {
        const int b = c % 3;
        if (c + 2 < NCHK) load_chunk((c + 2) % 3, (c + 2) * KC);
        if (c + 2 < NCHK)      CP_WAIT2();
        else if (c + 1 < NCHK) CP_WAIT1();
        else                   CP_WAIT0();
        __syncthreads();

        const uint32_t aBh = smb + (uint32_t)(b * BUF_E) * 2u;
        const uint32_t aBl = aBh + (uint32_t)TILE_A * 2u;
        const uint32_t bBh = aBh + (uint32_t)(2 * TILE_A) * 2u;

        #pragma unroll
        for (int ks = 0; ks < KC; ks += 16) {
            const int arow = wm + (lane & 15);
            const int acol = ks + ((lane >> 4) << 3);
            uint32_t ah[MI][4], al[MI][4];
            #pragma unroll
            for (int mi = 0; mi < MI; mi++) {
                uint32_t off = (uint32_t)((arow + mi * 16) * AST + acol) * 2u;
                ldmx4(ah[mi], aBh + off);
                ldmx4(al[mi], aBl + off);
            }
            const int brow = wn + (lane & 7) + ((lane & 16) ? 8 : 0);
            const int bcol = ks + ((lane & 8) ? 8 : 0);
            uint32_t bh[2][4];
            #pragma unroll
            for (int ni = 0; ni < 2; ni++) {
                uint32_t off = (uint32_t)((brow + ni * 16) * AST + bcol) * 2u;
                ldmx4(bh[ni], bBh + off);
            }
            #pragma unroll
            for (int mi = 0; mi < MI; mi++) {
                #pragma unroll
                for (int nj = 0; nj < 4; nj++) {
                    const uint32_t* ph = &bh[nj >> 1][(nj & 1) * 2];
                    mma16816(acc[mi][nj], ah[mi], ph);
                    mma16816(acc[mi][nj], al[mi], ph);
                }
            }
        }
        __syncthreads();
    }

    const int r0 = bm0 + wm + (lane >> 2);
    const int c0 = bn0 + wn + (lane & 3) * 2;
    #pragma unroll
    for (int mi = 0; mi < MI; mi++) {
        #pragma unroll
        for (int nj = 0; nj < 4; nj++) {
            int row = r0 + mi * 16;
            int col = c0 + nj * 8;
            float b0 = bias[col], b1 = bias[col + 1];
            float2 v0 = make_float2(acc[mi][nj][0] + b0, acc[mi][nj][1] + b1);
            float2 v1 = make_float2(acc[mi][nj][2] + b0, acc[mi][nj][3] + b1);
            *reinterpret_cast<float2*>(&C[(size_t)row * N + col]) = v0;
            *reinterpret_cast<float2*>(&C[(size_t)(row + 8) * N + col]) = v1;
        }
    }
}

// smem bytes: 3 buffers x (2*BM + 128) * AST * 2 bytes
#define GSMEM(BM) ((2 * BM + 128) * AST * 6)

// ---------------------------------------------------------------------------
// chunk_sum: per-chunk (C=64) KV / K sums. grid (NCH, HEADS) = 256 blocks.
// Thread map: d = tid>>2, eg = (tid&3)*16  -> coalesced float4 stores.
// ---------------------------------------------------------------------------
__global__ __launch_bounds__(256)
void chunk_sum_kernel() {
    extern __shared__ float smf[];
    float* rk = smf;                 // [64][64]
    float* vv = rk + CHUNK * DDIM;   // [64][64]
    float* cw = vv + CHUNK * DDIM;   // [64]
    float* sw = cw + CHUNK;          // [64]

    const int c = blockIdx.x, h = blockIdx.y, tid = threadIdx.x;

    for (int t = tid; t < CHUNK * DDIM; t += 256) {
        int i = t >> 6, d = t & 63;
        const float* row = g_qkv + (size_t)(c * CHUNK + i) * E3 + h * DDIM;
        rk[t] = fmaxf(row[EDIM + d], 0.f);
        vv[t] = row[2 * EDIM + d];
    }
    if (tid < CHUNK) {
        float th = (float)(c * CHUNK + tid) * THETA_SCALE;
        cw[tid] = cosf(th);
        sw[tid] = sinf(th);
    }
    __syncthreads();

    const int d  = tid >> 2;          // 0..63
    const int eg = (tid & 3) << 4;    // 0,16,32,48
    float aC[16], aS[16];
    #pragma unroll
    for (int e = 0; e < 16; e++) { aC[e] = 0.f; aS[e] = 0.f; }

    for (int i = 0; i < CHUNK; i++) {
        float kd = rk[i * DDIM + d];
        float kc = kd * cw[i];
        float ks = kd * sw[i];
        const float4* vp = reinterpret_cast<const float4*>(&vv[i * DDIM + eg]);
        #pragma unroll
        for (int e4 = 0; e4 < 4; e4++) {
            float4 v4 = vp[e4];
            aC[e4 * 4 + 0] += kc * v4.x; aC[e4 * 4 + 1] += kc * v4.y;
            aC[e4 * 4 + 2] += kc * v4.z; aC[e4 * 4 + 3] += kc * v4.w;
            aS[e4 * 4 + 0] += ks * v4.x; aS[e4 * 4 + 1] += ks * v4.y;
            aS[e4 * 4 + 2] += ks * v4.z; aS[e4 * 4 + 3] += ks * v4.w;
        }
    }

    size_t base = (size_t)(h * NCH + c) * 2 * DDIM * DDIM;
    float4* pc = reinterpret_cast<float4*>(&g_ckv[base + d * DDIM + eg]);
    float4* ps = reinterpret_cast<float4*>(&g_ckv[base + DDIM * DDIM + d * DDIM + eg]);
    #pragma unroll
    for (int e4 = 0; e4 < 4; e4++) {
        pc[e4] = make_float4(aC[e4 * 4 + 0], aC[e4 * 4 + 1], aC[e4 * 4 + 2], aC[e4 * 4 + 3]);
        ps[e4] = make_float4(aS[e4 * 4 + 0], aS[e4 * 4 + 1], aS[e4 * 4 + 2], aS[e4 * 4 + 3]);
    }

    if (tid < DDIM) {
        float sc = 0.f, ss = 0.f;
        for (int i = 0; i < CHUNK; i++) {
            float kd = rk[i * DDIM + tid];
            sc += kd * cw[i];
            ss += kd * sw[i];
        }
        size_t kb = (size_t)(h * NCH + c) * 2 * DDIM;
        g_ck[kb + tid]        = sc;
        g_ck[kb + DDIM + tid] = ss;
    }
}

// ---------------------------------------------------------------------------
// scan: exclusive prefix over 32 chunks, split across 2 threads per lane
// (chunks 0-15 / 16-31) with smem carry. grid 512 x 256, 16 regs live/thread.
// ---------------------------------------------------------------------------
__global__ __launch_bounds__(256)
void scan_kernel() {
    __shared__ float carry[128];
    const int h  = blockIdx.x >> 6;            // 8 heads x 64 blocks
    const int L0 = (blockIdx.x & 63) * 128;    // lane base (128 lanes per block)
    const int tid = threadIdx.x;
    const int KVSZ = 2 * DDIM * DDIM;          // 8192 lanes per (h,chunk)

    const int half = tid >> 7;                 // 0: chunks 0-15, 1: chunks 16-31
    const int lane = L0 + (tid & 127);
    const int cbase = half * 16;

    float v[16];
    #pragma unroll
    for (int c = 0; c < 16; c++)
        v[c] = g_ckv[(size_t)(h * NCH + cbase + c) * KVSZ + lane];

    if (half == 0) {
        float run = 0.f;
        #pragma unroll
        for (int c = 0; c < 16; c++) {
            g_pkv[(size_t)(h * NCH + c) * KVSZ + lane] = run;
            run += v[c];
        }
        carry[tid] = run;
    }
    __syncthreads();
    if (half == 1) {
        float run = carry[tid - 128];
        #pragma unroll
        for (int c = 0; c < 16; c++) {
            g_pkv[(size_t)(h * NCH + 16 + c) * KVSZ + lane] = run;
            run += v[c];
        }
    }

    // small K-sum scan: one block per head handles all 128 lanes serially
    if ((blockIdx.x & 63) == 0 && tid < 2 * DDIM) {
        const int KSZ = 2 * DDIM;
        float w[NCH];
        #pragma unroll
        for (int c = 0; c < NCH; c++)
            w[c] = g_ck[(size_t)(h * NCH + c) * KSZ + tid];
        float r2 = 0.f;
        #pragma unroll
        for (int c = 0; c < NCH; c++) {
            g_pk[(size_t)(h * NCH + c) * KSZ + tid] = r2;
            r2 += w[c];
        }
    }
}

// ---------------------------------------------------------------------------
// chunk_out (C=64): register-tiled, predicated-causal, fused fp16-split out.
// grid (NCH, HEADS) = 256 blocks, 256 threads.
// ---------------------------------------------------------------------------
#define RQT_STRIDE 68
#define S_STRIDE   66

__global__ __launch_bounds__(256)
void chunk_out_kernel() {
    extern __shared__ float smf[];
    float* rqT = smf;                       // [64][68]
    float* rkT = rqT + DDIM * RQT_STRIDE;   // [64][68]
    float* vv  = rkT + DDIM * RQT_STRIDE;   // [64][64]
    float* S   = vv + CHUNK * DDIM;         // [64][66]
    float* KVc = S + CHUNK * S_STRIDE;      // [64][64]
    float* KVs = KVc + DDIM * DDIM;         // [64][64]
    float* K0c = KVs + DDIM * DDIM;         // [64]
    float* K0s = K0c + DDIM;                // [64]
    float* cw  = K0s + DDIM;                // [64]
    float* sw  = cw + CHUNK;                // [64]
    float* nrm = sw + CHUNK;                // [64]

    const int c = blockIdx.x, h = blockIdx.y, tid = threadIdx.x;

    for (int t = tid; t < CHUNK * DDIM; t += 256) {
        int i = t >> 6, d = t & 63;
        const float* row = g_qkv + (size_t)(c * CHUNK + i) * E3 + h * DDIM;
        rqT[d * RQT_STRIDE + i] = fmaxf(row[d], 0.f);
        rkT[d * RQT_STRIDE + i] = fmaxf(row[EDIM + d], 0.f);
        vv[i * DDIM + d]        = row[2 * EDIM + d];
    }
    if (tid < CHUNK) {
        float th = (float)(c * CHUNK + tid) * THETA_SCALE;
        cw[tid] = cosf(th);
        sw[tid] = sinf(th);
    }
    {
        const float* base = g_pkv + (size_t)(h * NCH + c) * 2 * DDIM * DDIM;
        for (int t = tid; t < 2 * DDIM * DDIM; t += 256) {
            if (t < DDIM * DDIM) KVc[t] = base[t];
            else                 KVs[t - DDIM * DDIM] = base[t];
        }
        const float* kb = g_pk + (size_t)(h * NCH + c) * 2 * DDIM;
        if (tid < 2 * DDIM) {
            if (tid < DDIM) K0c[tid] = kb[tid];
            else            K0s[tid - DDIM] = kb[tid];
        }
    }
    __syncthreads();

    // ---- phase 1: S[i][j] (j<=i), 4x4 tiles on a 16x16 thread grid
    {
        const int ti = tid >> 4, tj = tid & 15;
        const int i0 = ti * 4, j0 = tj * 4;
        if (j0 <= i0 + 3) {
            float acc[4][4];
            #pragma unroll
            for (int r = 0; r < 4; r++)
                #pragma unroll
                for (int q = 0; q < 4; q++) acc[r][q] = 0.f;

            for (int d = 0; d < DDIM; d++) {
                float4 a4 = *reinterpret_cast<const float4*>(&rqT[d * RQT_STRIDE + i0]);
                float4 b4 = *reinterpret_cast<const float4*>(&rkT[d * RQT_STRIDE + j0]);
                float a[4] = {a4.x, a4.y, a4.z, a4.w};
                float b[4] = {b4.x, b4.y, b4.z, b4.w};
                #pragma unroll
                for (int r = 0; r < 4; r++)
                    #pragma unroll
                    for (int q = 0; q < 4; q++)
                        acc[r][q] += a[r] * b[q];
            }
            #pragma unroll
            for (int r = 0; r < 4; r++) {
                int i = i0 + r;
                float ci = cw[i], si = sw[i];
                #pragma unroll
                for (int q = 0; q < 4; q++) {
                    int j = j0 + q;
                    if (j <= i)
                        S[i * S_STRIDE + j] = acc[r][q] * (ci * cw[j] + si * sw[j]);
                }
            }
        }
    }
    __syncthreads();

    // ---- phase 2: nrm
    if (tid < CHUNK) {
        const int i = tid;
        float dc = 0.f, ds = 0.f;
        for (int d = 0; d < DDIM; d++) {
            float q = rqT[d * RQT_STRIDE + i];
            dc += q * K0c[d];
            ds += q * K0s[d];
        }
        float n = cw[i] * dc + sw[i] * ds;
        for (int j = 0; j <= i; j++) n += S[i * S_STRIDE + j];
        nrm[i] = n;
    }
    __syncthreads();

    // ---- phase 3: 2 rows x 8 cols per thread
    const int tx = tid & 7, ty = tid >> 3;
    const int e0 = tx * 8, i0 = ty * 2;

    float tC[2][8], tS[2][8], tI[2][8];
    #pragma unroll
    for (int r = 0; r < 2; r++)
        #pragma unroll
        for (int e = 0; e < 8; e++) { tC[r][e] = 0.f; tS[r][e] = 0.f; tI[r][e] = 0.f; }

    for (int d = 0; d < DDIM; d++) {
        float2 q2 = *reinterpret_cast<const float2*>(&rqT[d * RQT_STRIDE + i0]);
        float qr[2] = {q2.x, q2.y};
        float4 c0 = *reinterpret_cast<const float4*>(&KVc[d * DDIM + e0]);
        float4 c1 = *reinterpret_cast<const float4*>(&KVc[d * DDIM + e0 + 4]);
        float4 s0 = *reinterpret_cast<const float4*>(&KVs[d * DDIM + e0]);
        float4 s1 = *reinterpret_cast<const float4*>(&KVs[d * DDIM + e0 + 4]);
        float cv[8] = {c0.x, c0.y, c0.z, c0.w, c1.x, c1.y, c1.z, c1.w};
        float sv[8] = {s0.x, s0.y, s0.z, s0.w, s1.x, s1.y, s1.z, s1.w};
        #pragma unroll
        for (int r = 0; r < 2; r++)
            #pragma unroll
            for (int e = 0; e < 8; e++) {
                tC[r][e] += qr[r] * cv[e];
                tS[r][e] += qr[r] * sv[e];
            }
    }

    for (int j = 0; j <= i0; j++) {
        float sr[2];
        #pragma unroll
        for (int r = 0; r < 2; r++) sr[r] = S[(i0 + r) * S_STRIDE + j];
        float4 v0 = *reinterpret_cast<const float4*>(&vv[j * DDIM + e0]);
        float4 v1 = *reinterpret_cast<const float4*>(&vv[j * DDIM + e0 + 4]);
        float ve[8] = {v0.x, v0.y, v0.z, v0.w, v1.x, v1.y, v1.z, v1.w};
        #pragma unroll
        for (int r = 0; r < 2; r++)
            #pragma unroll
            for (int e = 0; e < 8; e++)
                tI[r][e] += sr[r] * ve[e];
    }
    {   // tail j = i0+1, valid only for r=1
        const int j = i0 + 1;
        float s1 = S[(i0 + 1) * S_STRIDE + j];
        float4 v0 = *reinterpret_cast<const float4*>(&vv[j * DDIM + e0]);
        float4 v1 = *reinterpret_cast<const float4*>(&vv[j * DDIM + e0 + 4]);
        float ve[8] = {v0.x, v0.y, v0.z, v0.w, v1.x, v1.y, v1.z, v1.w};
        #pragma unroll
        for (int e = 0; e < 8; e++)
            tI[1][e] += s1 * ve[e];
    }

    // ---- epilogue: combine, normalize, fp16 hi/lo split, store
    #pragma unroll
    for (int r = 0; r < 2; r++) {
        const int i = i0 + r;
        float ci = cw[i], si = sw[i];
        float inv = 1.0f / (nrm[i] + 1e-6f);
        uint32_t ph[4], pl[4];
        #pragma unroll
        for (int e2 = 0; e2 < 4; e2++) {
            float v0 = (ci * tC[r][e2 * 2 + 0] + si * tS[r][e2 * 2 + 0] + tI[r][e2 * 2 + 0]) * inv;
            float v1 = (ci * tC[r][e2 * 2 + 1] + si * tS[r][e2 * 2 + 1] + tI[r][e2 * 2 + 1]) * inv;
            __half h0 = __float2half(v0);
            __half h1 = __float2half(v1);
            __half l0 = __float2half(v0 - __half2float(h0));
            __half l1 = __float2half(v1 - __half2float(h1));
            ph[e2] = (uint32_t)__half_as_ushort(h0) |
                     ((uint32_t)__half_as_ushort(h1) << 16);
            pl[e2] = (uint32_t)__half_as_ushort(l0) |
                     ((uint32_t)__half_as_ushort(l1) << 16);
        }
        size_t base = (size_t)(c * CHUNK + i) * EDIM + h * DDIM + e0;
        *reinterpret_cast<uint4*>(&g_ah[base]) = make_uint4(ph[0], ph[1], ph[2], ph[3]);
        *reinterpret_cast<uint4*>(&g_al[base]) = make_uint4(pl[0], pl[1], pl[2], pl[3]);
    }
}

// ---------------------------------------------------------------------------

static const int SMEM_SUM = (2 * CHUNK * DDIM + 2 * CHUNK) * (int)sizeof(float);
static const int SMEM_OUT = (2 * DDIM * RQT_STRIDE + CHUNK * DDIM + CHUNK * S_STRIDE +
                             2 * DDIM * DDIM + 2 * DDIM + 3 * CHUNK) * (int)sizeof(float);

extern "C" void kernel_launch(void* const* d_in, const int* in_sizes, int n_in,
                              void* d_out, int out_size) {
    (void)in_sizes; (void)n_in; (void)out_size;
    const float* x    = (const float*)d_in[0];
    const float* Wqkv = (const float*)d_in[1];
    const float* bqkv = (const float*)d_in[2];
    const float* Wout = (const float*)d_in[3];
    const float* bout = (const float*)d_in[4];
    float* out = (float*)d_out;

    float* qkv_ptr;
    cudaGetSymbolAddress((void**)&qkv_ptr, g_qkv);
    __half *xh, *xl, *wqh, *woh, *ah, *al;
    cudaGetSymbolAddress((void**)&xh, g_xh);
    cudaGetSymbolAddress((void**)&xl, g_xl);
    cudaGetSymbolAddress((void**)&wqh, g_wqh);
    cudaGetSymbolAddress((void**)&woh, g_woh);
    cudaGetSymbolAddress((void**)&ah, g_ah);
    cudaGetSymbolAddress((void**)&al, g_al);

    cudaFuncSetAttribute(chunk_sum_kernel,
                         cudaFuncAttributeMaxDynamicSharedMemorySize, SMEM_SUM);
    cudaFuncSetAttribute(chunk_out_kernel,
                         cudaFuncAttributeMaxDynamicSharedMemorySize, SMEM_OUT);
    cudaFuncSetAttribute((const void*)mma_gemm_kernel<64>,
                         cudaFuncAttributeMaxDynamicSharedMemorySize, GSMEM(64));
    cudaFuncSetAttribute((const void*)mma_gemm_kernel<32>,
                         cudaFuncAttributeMaxDynamicSharedMemorySize, GSMEM(32));

    // fused fp16 splits: x hi/lo + Wqkv^T hi + Wout^T hi, one launch
    split_all_kernel<<<1024 + 768 + 256, 256>>>(x, Wqkv, Wout);

    // 1) QKV GEMM: 64x128 tiles -> grid 384, 3 CTAs/SM, 3-stage pipeline
    mma_gemm_kernel<64><<<dim3(E3 / 128, LSEQ / 64), 256, GSMEM(64)>>>(
        xh, xl, wqh, bqkv, qkv_ptr, E3, EDIM);

    // 2) Chunked cosformer attention
    chunk_sum_kernel<<<dim3(NCH, HEADS), 256, SMEM_SUM>>>();
    scan_kernel<<<512, 256>>>();
    chunk_out_kernel<<<dim3(NCH, HEADS), 256, SMEM_OUT>>>();

    // 3) Output GEMM: 32x128 tiles -> grid 256, 3-stage pipeline
    mma_gemm_kernel<32><<<dim3(EDIM / 128, LSEQ / 32), 256, GSMEM(32)>>>(
        ah, al, woh, bout, out, EDIM, EDIM);
}

// round 14
// speedup vs baseline: 1.0197x; 1.0191x over previous
#include <cuda_runtime.h>
#include <cuda_fp16.h>
#include <cstdint>
#include <cstddef>

// Problem constants
#define LSEQ 2048
#define EDIM 512
#define HEADS 8
#define DDIM 64
#define E3   1536
#define CHUNK 64
#define NCH  32

#define THETA_SCALE 7.66990393942820573e-4f  // (pi/2)/2048

// ---------------- scratch (device globals; no allocs allowed) ----------------
__device__ float g_qkv[LSEQ * E3];
__device__ float g_ckv[HEADS * NCH * 2 * DDIM * DDIM];
__device__ float g_ck [HEADS * NCH * 2 * DDIM];
__device__ float g_pkv[HEADS * NCH * 2 * DDIM * DDIM];
__device__ float g_pk [HEADS * NCH * 2 * DDIM];

// fp16 split buffers (fp16x2 scheme: A = Ah + Al, B = Bh only)
__device__ __half g_xh[LSEQ * EDIM];
__device__ __half g_xl[LSEQ * EDIM];
__device__ __half g_wqh[E3 * EDIM];   // Wqkv^T  [1536][512]
__device__ __half g_woh[EDIM * EDIM]; // Wout^T  [512][512]
__device__ __half g_ah[LSEQ * EDIM];  // attention out hi/lo
__device__ __half g_al[LSEQ * EDIM];

// ---------------- low-level helpers ----------------
__device__ __forceinline__ uint32_t smem_u32(const void* p) {
    uint32_t a;
    asm("{ .reg .u64 t; cvta.to.shared.u64 t, %1; cvt.u32.u64 %0, t; }"
        : "=r"(a) : "l"(p));
    return a;
}
#define CP_ASYNC16(dst, src) \
    asm volatile("cp.async.cg.shared.global [%0], [%1], 16;" :: "r"(dst), "l"(src))
#define CP_COMMIT() asm volatile("cp.async.commit_group;" ::: "memory")
#define CP_WAIT0()  asm volatile("cp.async.wait_group 0;" ::: "memory")
#define CP_WAIT1()  asm volatile("cp.async.wait_group 1;" ::: "memory")
#define CP_WAIT2()  asm volatile("cp.async.wait_group 2;" ::: "memory")

__device__ __forceinline__ void ldmx4(uint32_t* r, uint32_t addr) {
    asm volatile("ldmatrix.sync.aligned.m8n8.x4.shared.b16 {%0,%1,%2,%3}, [%4];"
                 : "=r"(r[0]), "=r"(r[1]), "=r"(r[2]), "=r"(r[3]) : "r"(addr));
}
__device__ __forceinline__ void mma16816(float* c, const uint32_t* a, const uint32_t* b) {
    asm volatile(
        "mma.sync.aligned.m16n8k16.row.col.f32.f16.f16.f32 "
        "{%0,%1,%2,%3}, {%4,%5,%6,%7}, {%8,%9}, {%0,%1,%2,%3};"
        : "+f"(c[0]), "+f"(c[1]), "+f"(c[2]), "+f"(c[3])
        : "r"(a[0]), "r"(a[1]), "r"(a[2]), "r"(a[3]), "r"(b[0]), "r"(b[1]));
}

// ---------------- fused split kernel: x hi/lo + both weight transposes ------
__device__ __forceinline__ void transpose_split_tile(
    const float* __restrict__ W, __half* __restrict__ hiT,
    int K, int N, int bx, int by, float (*t)[33]) {
    const int tx = threadIdx.x & 31, ty = threadIdx.x >> 5;  // (32, 8)
    const int n0 = bx * 32, k0 = by * 32;
    #pragma unroll
    for (int j = 0; j < 4; j++)
        t[ty + 8 * j][tx] = W[(size_t)(k0 + ty + 8 * j) * N + n0 + tx];
    __syncthreads();
    #pragma unroll
    for (int j = 0; j < 4; j++)
        hiT[(size_t)(n0 + ty + 8 * j) * K + k0 + tx] = __float2half(t[tx][ty + 8 * j]);
}

__global__ __launch_bounds__(256)
void split_all_kernel(const float* __restrict__ x,
                      const float* __restrict__ Wqkv,
                      const float* __restrict__ Wout) {
    __shared__ float t[32][33];
    const int b = blockIdx.x;
    if (b < 1024) {
        int i = b * 1024 + threadIdx.x * 4;
        float4 a4 = *reinterpret_cast<const float4*>(&x[i]);
        float av[4] = {a4.x, a4.y, a4.z, a4.w};
        __half hv[4], lv[4];
        #pragma unroll
        for (int k = 0; k < 4; k++) {
            hv[k] = __float2half(av[k]);
            lv[k] = __float2half(av[k] - __half2float(hv[k]));
        }
        *reinterpret_cast<uint2*>(&g_xh[i]) = *reinterpret_cast<uint2*>(hv);
        *reinterpret_cast<uint2*>(&g_xl[i]) = *reinterpret_cast<uint2*>(lv);
    } else if (b < 1024 + 768) {
        int tt = b - 1024;                 // Wqkv: K=512, N=1536 -> 48 x 16 tiles
        transpose_split_tile(Wqkv, g_wqh, EDIM, E3, tt % 48, tt / 48, t);
    } else {
        int tt = b - 1024 - 768;           // Wout: K=512, N=512 -> 16 x 16 tiles
        transpose_split_tile(Wout, g_woh, EDIM, EDIM, tt % 16, tt / 16, t);
    }
}

// ---------------- mma.sync fp16x2 GEMM: C[M,N] = A @ Bt^T + bias --------------
// A = Ah + Al (fp16 hi/lo), B = Bh (single fp16). 2 MMAs per tile.
// BN = 128 fixed. 8 warps as 2(M) x 4(N): warp tile (BM/2) x 32.
// K-chunk 32, 3-stage cp.async pipeline, 3 CTAs/SM. (R10-proven form.)
#define KC 32
#define AST 40   // smem row stride in fp16 elems

template<int BM>
__global__ __launch_bounds__(256, 3)
void mma_gemm_kernel(const __half* __restrict__ Ah, const __half* __restrict__ Al,
                     const __half* __restrict__ Bh,
                     const float* __restrict__ bias, float* __restrict__ C,
                     int N, int K) {
    constexpr int MI = BM / 32;
    constexpr int TILE_A = BM * AST;
    constexpr int TILE_B = 128 * AST;
    constexpr int BUF_E  = 2 * TILE_A + TILE_B;

    extern __shared__ __half smem[];
    const int tid = threadIdx.x;
    const int wid = tid >> 5, lane = tid & 31;
    const int bn0 = blockIdx.x * 128, bm0 = blockIdx.y * BM;
    const int wm = (wid & 1) * (BM / 2);
    const int wn = (wid >> 1) * 32;

    const uint32_t smb = smem_u32(smem);
    const int NCHK = K / KC;

    float acc[MI][4][4];
    #pragma unroll
    for (int mi = 0; mi < MI; mi++)
        #pragma unroll
        for (int nj = 0; nj < 4; nj++)
            #pragma unroll
            for (int r = 0; r < 4; r++) acc[mi][nj][r] = 0.f;

    const __half* srcs[3] = {Ah, Al, Bh};
    const int  srow[3] = {bm0, bm0, bn0};
    const int  titem[3] = {BM * KC / 8, BM * KC / 8, 128 * KC / 8};
    const uint32_t toff[3] = {0u, (uint32_t)TILE_A, (uint32_t)(2 * TILE_A)};

    auto load_chunk = [&](int b, int k0) {
        #pragma unroll
        for (int t = 0; t < 3; t++) {
            const __half* s = srcs[t];
            uint32_t dbase = smb + (uint32_t)(b * BUF_E + toff[t]) * 2u;
            const int nit = titem[t];
            for (int item = tid; item < nit; item += 256) {
                int row = item >> 2, sub = item & 3;
                uint32_t d = dbase + (uint32_t)(row * AST + sub * 8) * 2u;
                const void* g = (const void*)(s + (size_t)(srow[t] + row) * K + k0 + sub * 8);
                CP_ASYNC16(d, g);
            }
        }
        CP_COMMIT();
    };

    load_chunk(0, 0);
    load_chunk(1, KC);

    for (int c = 0; c < NCHK; c++) {
        const int b = c % 3;
        if (c + 2 < NCHK) load_chunk((c + 2) % 3, (c + 2) * KC);
        if (c + 2 < NCHK)      CP_WAIT2();
        else if (c + 1 < NCHK) CP_WAIT1();
        else                   CP_WAIT0();
        __syncthreads();

        const uint32_t aBh = smb + (uint32_t)(b * BUF_E) * 2u;
        const uint32_t aBl = aBh + (uint32_t)TILE_A * 2u;
        const uint32_t bBh = aBh + (uint32_t)(2 * TILE_A) * 2u;

        #pragma unroll
        for (int ks = 0; ks < KC; ks += 16) {
            const int arow = wm + (lane & 15);
            const int acol = ks + ((lane >> 4) << 3);
            uint32_t ah[MI][4], al[MI][4];
            #pragma unroll
            for (int mi = 0; mi < MI; mi++) {
                uint32_t off = (uint32_t)((arow + mi * 16) * AST + acol) * 2u;
                ldmx4(ah[mi], aBh + off);
                ldmx4(al[mi], aBl + off);
            }
            const int brow = wn + (lane & 7) + ((lane & 16) ? 8 : 0);
            const int bcol = ks + ((lane & 8) ? 8 : 0);
            uint32_t bh[2][4];
            #pragma unroll
            for (int ni = 0; ni < 2; ni++) {
                uint32_t off = (uint32_t)((brow + ni * 16) * AST + bcol) * 2u;
                ldmx4(bh[ni], bBh + off);
            }
            #pragma unroll
            for (int mi = 0; mi < MI; mi++) {
                #pragma unroll
                for (int nj = 0; nj < 4; nj++) {
                    const uint32_t* ph = &bh[nj >> 1][(nj & 1) * 2];
                    mma16816(acc[mi][nj], ah[mi], ph);
                    mma16816(acc[mi][nj], al[mi], ph);
                }
            }
        }
        __syncthreads();
    }

    const int r0 = bm0 + wm + (lane >> 2);
    const int c0 = bn0 + wn + (lane & 3) * 2;
    #pragma unroll
    for (int mi = 0; mi < MI; mi++) {
        #pragma unroll
        for (int nj = 0; nj < 4; nj++) {
            int row = r0 + mi * 16;
            int col = c0 + nj * 8;
            float b0 = bias[col], b1 = bias[col + 1];
            float2 v0 = make_float2(acc[mi][nj][0] + b0, acc[mi][nj][1] + b1);
            float2 v1 = make_float2(acc[mi][nj][2] + b0, acc[mi][nj][3] + b1);
            *reinterpret_cast<float2*>(&C[(size_t)row * N + col]) = v0;
            *reinterpret_cast<float2*>(&C[(size_t)(row + 8) * N + col]) = v1;
        }
    }
}

// smem bytes: 3 buffers x (2*BM + 128) * AST * 2 bytes
#define GSMEM(BM) ((2 * BM + 128) * AST * 6)

// ---------------------------------------------------------------------------
// chunk_sum: per-chunk (C=64) KV / K sums. grid (NCH, HEADS) = 256 blocks.
// (R10 form: d = tid&63, eg = (tid>>6)*16.)
// ---------------------------------------------------------------------------
__global__ __launch_bounds__(256)
void chunk_sum_kernel() {
    extern __shared__ float smf[];
    float* rk = smf;                 // [64][64]
    float* vv = rk + CHUNK * DDIM;   // [64][64]
    float* cw = vv + CHUNK * DDIM;   // [64]
    float* sw = cw + CHUNK;          // [64]

    const int c = blockIdx.x, h = blockIdx.y, tid = threadIdx.x;

    for (int t = tid; t < CHUNK * DDIM; t += 256) {
        int i = t >> 6, d = t & 63;
        const float* row = g_qkv + (size_t)(c * CHUNK + i) * E3 + h * DDIM;
        rk[t] = fmaxf(row[EDIM + d], 0.f);
        vv[t] = row[2 * EDIM + d];
    }
    if (tid < CHUNK) {
        float th = (float)(c * CHUNK + tid) * THETA_SCALE;
        cw[tid] = cosf(th);
        sw[tid] = sinf(th);
    }
    __syncthreads();

    const int d  = tid & 63;
    const int eg = (tid >> 6) << 4;
    float aC[16], aS[16];
    #pragma unroll
    for (int e = 0; e < 16; e++) { aC[e] = 0.f; aS[e] = 0.f; }

    for (int i = 0; i < CHUNK; i++) {
        float kd = rk[i * DDIM + d];
        float kc = kd * cw[i];
        float ks = kd * sw[i];
        const float4* vp = reinterpret_cast<const float4*>(&vv[i * DDIM + eg]);
        #pragma unroll
        for (int e4 = 0; e4 < 4; e4++) {
            float4 v4 = vp[e4];
            aC[e4 * 4 + 0] += kc * v4.x; aC[e4 * 4 + 1] += kc * v4.y;
            aC[e4 * 4 + 2] += kc * v4.z; aC[e4 * 4 + 3] += kc * v4.w;
            aS[e4 * 4 + 0] += ks * v4.x; aS[e4 * 4 + 1] += ks * v4.y;
            aS[e4 * 4 + 2] += ks * v4.z; aS[e4 * 4 + 3] += ks * v4.w;
        }
    }

    size_t base = (size_t)(h * NCH + c) * 2 * DDIM * DDIM;
    #pragma unroll
    for (int e = 0; e < 16; e++) {
        g_ckv[base + d * DDIM + eg + e]               = aC[e];
        g_ckv[base + DDIM * DDIM + d * DDIM + eg + e] = aS[e];
    }

    if (tid < DDIM) {
        float sc = 0.f, ss = 0.f;
        for (int i = 0; i < CHUNK; i++) {
            float kd = rk[i * DDIM + tid];
            sc += kd * cw[i];
            ss += kd * sw[i];
        }
        size_t kb = (size_t)(h * NCH + c) * 2 * DDIM;
        g_ck[kb + tid]        = sc;
        g_ck[kb + DDIM + tid] = ss;
    }
}

// ---------------------------------------------------------------------------
// scan: exclusive prefix over 32 chunks. grid 256 x 256, one thread per lane.
// (R10 form — best measured: 6.8us.)
// ---------------------------------------------------------------------------
__global__ __launch_bounds__(256)
void scan_kernel() {
    const int h = blockIdx.x >> 5;
    const int idx = (blockIdx.x & 31) * 256 + threadIdx.x;  // 0..8191
    const int KVSZ = 2 * DDIM * DDIM;  // 8192

    float v[NCH];
    #pragma unroll
    for (int c = 0; c < NCH; c++)
        v[c] = g_ckv[(size_t)(h * NCH + c) * KVSZ + idx];
    float run = 0.f;
    #pragma unroll
    for (int c = 0; c < NCH; c++) {
        g_pkv[(size_t)(h * NCH + c) * KVSZ + idx] = run;
        run += v[c];
    }

    if ((blockIdx.x & 31) == 0 && threadIdx.x < 2 * DDIM) {
        const int t = threadIdx.x;
        const int KSZ = 2 * DDIM;
        float w[NCH];
        #pragma unroll
        for (int c = 0; c < NCH; c++)
            w[c] = g_ck[(size_t)(h * NCH + c) * KSZ + t];
        float r2 = 0.f;
        #pragma unroll
        for (int c = 0; c < NCH; c++) {
            g_pk[(size_t)(h * NCH + c) * KSZ + t] = r2;
            r2 += w[c];
        }
    }
}

// ---------------------------------------------------------------------------
// chunk_out (C=64): register-tiled, predicated-causal, fused fp16-split out.
// grid (NCH, HEADS) = 256 blocks, 256 threads.
// Phase 2 (nrm) now parallelized: 4 threads per row via smem partials.
// ---------------------------------------------------------------------------
#define RQT_STRIDE 68
#define S_STRIDE   66

__global__ __launch_bounds__(256)
void chunk_out_kernel() {
    extern __shared__ float smf[];
    float* rqT = smf;                       // [64][68]
    float* rkT = rqT + DDIM * RQT_STRIDE;   // [64][68]
    float* vv  = rkT + DDIM * RQT_STRIDE;   // [64][64]
    float* S   = vv + CHUNK * DDIM;         // [64][66]
    float* KVc = S + CHUNK * S_STRIDE;      // [64][64]
    float* KVs = KVc + DDIM * DDIM;         // [64][64]
    float* K0c = KVs + DDIM * DDIM;         // [64]
    float* K0s = K0c + DDIM;                // [64]
    float* cw  = K0s + DDIM;                // [64]
    float* sw  = cw + CHUNK;                // [64]
    float* nrm = sw + CHUNK;                // [64]
    float* nrm4 = nrm + CHUNK;              // [4][64] partials

    const int c = blockIdx.x, h = blockIdx.y, tid = threadIdx.x;

    for (int t = tid; t < CHUNK * DDIM; t += 256) {
        int i = t >> 6, d = t & 63;
        const float* row = g_qkv + (size_t)(c * CHUNK + i) * E3 + h * DDIM;
        rqT[d * RQT_STRIDE + i] = fmaxf(row[d], 0.f);
        rkT[d * RQT_STRIDE + i] = fmaxf(row[EDIM + d], 0.f);
        vv[i * DDIM + d]        = row[2 * EDIM + d];
    }
    if (tid < CHUNK) {
        float th = (float)(c * CHUNK + tid) * THETA_SCALE;
        cw[tid] = cosf(th);
        sw[tid] = sinf(th);
    }
    {
        const float* base = g_pkv + (size_t)(h * NCH + c) * 2 * DDIM * DDIM;
        for (int t = tid; t < 2 * DDIM * DDIM; t += 256) {
            if (t < DDIM * DDIM) KVc[t] = base[t];
            else                 KVs[t - DDIM * DDIM] = base[t];
        }
        const float* kb = g_pk + (size_t)(h * NCH + c) * 2 * DDIM;
        if (tid < 2 * DDIM) {
            if (tid < DDIM) K0c[tid] = kb[tid];
            else            K0s[tid - DDIM] = kb[tid];
        }
    }
    __syncthreads();

    // ---- phase 1: S[i][j] (j<=i), 4x4 tiles on a 16x16 thread grid
    {
        const int ti = tid >> 4, tj = tid & 15;
        const int i0 = ti * 4, j0 = tj * 4;
        if (j0 <= i0 + 3) {
            float acc[4][4];
            #pragma unroll
            for (int r = 0; r < 4; r++)
                #pragma unroll
                for (int q = 0; q < 4; q++) acc[r][q] = 0.f;

            for (int d = 0; d < DDIM; d++) {
                float4 a4 = *reinterpret_cast<const float4*>(&rqT[d * RQT_STRIDE + i0]);
                float4 b4 = *reinterpret_cast<const float4*>(&rkT[d * RQT_STRIDE + j0]);
                float a[4] = {a4.x, a4.y, a4.z, a4.w};
                float b[4] = {b4.x, b4.y, b4.z, b4.w};
                #pragma unroll
                for (int r = 0; r < 4; r++)
                    #pragma unroll
                    for (int q = 0; q < 4; q++)
                        acc[r][q] += a[r] * b[q];
            }
            #pragma unroll
            for (int r = 0; r < 4; r++) {
                int i = i0 + r;
                float ci = cw[i], si = sw[i];
                #pragma unroll
                for (int q = 0; q < 4; q++) {
                    int j = j0 + q;
                    if (j <= i)
                        S[i * S_STRIDE + j] = acc[r][q] * (ci * cw[j] + si * sw[j]);
                }
            }
        }
    }
    __syncthreads();

    // ---- phase 2: nrm, 4 threads per row (d-slice of dot + j-slice of row sum)
    {
        const int i2 = tid & 63, qd = tid >> 6;   // row, quarter
        float dc = 0.f, ds = 0.f;
        #pragma unroll
        for (int dd = 0; dd < 16; dd++) {
            int d = qd * 16 + dd;
            float q = rqT[d * RQT_STRIDE + i2];
            dc += q * K0c[d];
            ds += q * K0s[d];
        }
        float part = cw[i2] * dc + sw[i2] * ds;
        int jbeg = qd * 16;
        int jend = (i2 < jbeg + 15) ? i2 : (jbeg + 15);
        for (int j = jbeg; j <= jend; j++) part += S[i2 * S_STRIDE + j];
        nrm4[qd * 64 + i2] = part;
    }
    __syncthreads();
    if (tid < CHUNK)
        nrm[tid] = nrm4[tid] + nrm4[64 + tid] + nrm4[128 + tid] + nrm4[192 + tid];
    __syncthreads();

    // ---- phase 3: 2 rows x 8 cols per thread
    const int tx = tid & 7, ty = tid >> 3;
    const int e0 = tx * 8, i0 = ty * 2;

    float tC[2][8], tS[2][8], tI[2][8];
    #pragma unroll
    for (int r = 0; r < 2; r++)
        #pragma unroll
        for (int e = 0; e < 8; e++) { tC[r][e] = 0.f; tS[r][e] = 0.f; tI[r][e] = 0.f; }

    for (int d = 0; d < DDIM; d++) {
        float2 q2 = *reinterpret_cast<const float2*>(&rqT[d * RQT_STRIDE + i0]);
        float qr[2] = {q2.x, q2.y};
        float4 c0 = *reinterpret_cast<const float4*>(&KVc[d * DDIM + e0]);
        float4 c1 = *reinterpret_cast<const float4*>(&KVc[d * DDIM + e0 + 4]);
        float4 s0 = *reinterpret_cast<const float4*>(&KVs[d * DDIM + e0]);
        float4 s1 = *reinterpret_cast<const float4*>(&KVs[d * DDIM + e0 + 4]);
        float cv[8] = {c0.x, c0.y, c0.z, c0.w, c1.x, c1.y, c1.z, c1.w};
        float sv[8] = {s0.x, s0.y, s0.z, s0.w, s1.x, s1.y, s1.z, s1.w};
        #pragma unroll
        for (int r = 0; r < 2; r++)
            #pragma unroll
            for (int e = 0; e < 8; e++) {
                tC[r][e] += qr[r] * cv[e];
                tS[r][e] += qr[r] * sv[e];
            }
    }

    for (int j = 0; j <= i0; j++) {
        float sr[2];
        #pragma unroll
        for (int r = 0; r < 2; r++) sr[r] = S[(i0 + r) * S_STRIDE + j];
        float4 v0 = *reinterpret_cast<const float4*>(&vv[j * DDIM + e0]);
        float4 v1 = *reinterpret_cast<const float4*>(&vv[j * DDIM + e0 + 4]);
        float ve[8] = {v0.x, v0.y, v0.z, v0.w, v1.x, v1.y, v1.z, v1.w};
        #pragma unroll
        for (int r = 0; r < 2; r++)
            #pragma unroll
            for (int e = 0; e < 8; e++)
                tI[r][e] += sr[r] * ve[e];
    }
    {   // tail j = i0+1, valid only for r=1
        const int j = i0 + 1;
        float s1 = S[(i0 + 1) * S_STRIDE + j];
        float4 v0 = *reinterpret_cast<const float4*>(&vv[j * DDIM + e0]);
        float4 v1 = *reinterpret_cast<const float4*>(&vv[j * DDIM + e0 + 4]);
        float ve[8] = {v0.x, v0.y, v0.z, v0.w, v1.x, v1.y, v1.z, v1.w};
        #pragma unroll
        for (int e = 0; e < 8; e++)
            tI[1][e] += s1 * ve[e];
    }

    // ---- epilogue: combine, normalize, fp16 hi/lo split, store
    #pragma unroll
    for (int r = 0; r < 2; r++) {
        const int i = i0 + r;
        float ci = cw[i], si = sw[i];
        float inv = 1.0f / (nrm[i] + 1e-6f);
        uint32_t ph[4], pl[4];
        #pragma unroll
        for (int e2 = 0; e2 < 4; e2++) {
            float v0 = (ci * tC[r][e2 * 2 + 0] + si * tS[r][e2 * 2 + 0] + tI[r][e2 * 2 + 0]) * inv;
            float v1 = (ci * tC[r][e2 * 2 + 1] + si * tS[r][e2 * 2 + 1] + tI[r][e2 * 2 + 1]) * inv;
            __half h0 = __float2half(v0);
            __half h1 = __float2half(v1);
            __half l0 = __float2half(v0 - __half2float(h0));
            __half l1 = __float2half(v1 - __half2float(h1));
            ph[e2] = (uint32_t)__half_as_ushort(h0) |
                     ((uint32_t)__half_as_ushort(h1) << 16);
            pl[e2] = (uint32_t)__half_as_ushort(l0) |
                     ((uint32_t)__half_as_ushort(l1) << 16);
        }
        size_t base = (size_t)(c * CHUNK + i) * EDIM + h * DDIM + e0;
        *reinterpret_cast<uint4*>(&g_ah[base]) = make_uint4(ph[0], ph[1], ph[2], ph[3]);
        *reinterpret_cast<uint4*>(&g_al[base]) = make_uint4(pl[0], pl[1], pl[2], pl[3]);
    }
}

// ---------------------------------------------------------------------------

static const int SMEM_SUM = (2 * CHUNK * DDIM + 2 * CHUNK) * (int)sizeof(float);
static const int SMEM_OUT = (2 * DDIM * RQT_STRIDE + CHUNK * DDIM + CHUNK * S_STRIDE +
                             2 * DDIM * DDIM + 2 * DDIM + 3 * CHUNK + 4 * CHUNK) * (int)sizeof(float);

extern "C" void kernel_launch(void* const* d_in, const int* in_sizes, int n_in,
                              void* d_out, int out_size) {
    (void)in_sizes; (void)n_in; (void)out_size;
    const float* x    = (const float*)d_in[0];
    const float* Wqkv = (const float*)d_in[1];
    const float* bqkv = (const float*)d_in[2];
    const float* Wout = (const float*)d_in[3];
    const float* bout = (const float*)d_in[4];
    float* out = (float*)d_out;

    float* qkv_ptr;
    cudaGetSymbolAddress((void**)&qkv_ptr, g_qkv);
    __half *xh, *xl, *wqh, *woh, *ah, *al;
    cudaGetSymbolAddress((void**)&xh, g_xh);
    cudaGetSymbolAddress((void**)&xl, g_xl);
    cudaGetSymbolAddress((void**)&wqh, g_wqh);
    cudaGetSymbolAddress((void**)&woh, g_woh);
    cudaGetSymbolAddress((void**)&ah, g_ah);
    cudaGetSymbolAddress((void**)&al, g_al);

    cudaFuncSetAttribute(chunk_sum_kernel,
                         cudaFuncAttributeMaxDynamicSharedMemorySize, SMEM_SUM);
    cudaFuncSetAttribute(chunk_out_kernel,
                         cudaFuncAttributeMaxDynamicSharedMemorySize, SMEM_OUT);
    cudaFuncSetAttribute((const void*)mma_gemm_kernel<64>,
                         cudaFuncAttributeMaxDynamicSharedMemorySize, GSMEM(64));
    cudaFuncSetAttribute((const void*)mma_gemm_kernel<32>,
                         cudaFuncAttributeMaxDynamicSharedMemorySize, GSMEM(32));

    // fused fp16 splits: x hi/lo + Wqkv^T hi + Wout^T hi, one launch
    split_all_kernel<<<1024 + 768 + 256, 256>>>(x, Wqkv, Wout);

    // 1) QKV GEMM: 64x128 tiles -> grid 384, 3 CTAs/SM, 3-stage pipeline
    mma_gemm_kernel<64><<<dim3(E3 / 128, LSEQ / 64), 256, GSMEM(64)>>>(
        xh, xl, wqh, bqkv, qkv_ptr, E3, EDIM);

    // 2) Chunked cosformer attention
    chunk_sum_kernel<<<dim3(NCH, HEADS), 256, SMEM_SUM>>>();
    scan_kernel<<<256, 256>>>();
    chunk_out_kernel<<<dim3(NCH, HEADS), 256, SMEM_OUT>>>();

    // 3) Output GEMM: 32x128 tiles -> grid 256, 3-stage pipeline
    mma_gemm_kernel<32><<<dim3(EDIM / 128, LSEQ / 32), 256, GSMEM(32)>>>(
        ah, al, woh, bout, out, EDIM, EDIM);
}

// round 15
// speedup vs baseline: 1.1277x; 1.1059x over previous
#include <cuda_runtime.h>
#include <cuda_fp16.h>
#include <cstdint>
#include <cstddef>

// Problem constants
#define LSEQ 2048
#define EDIM 512
#define HEADS 8
#define DDIM 64
#define E3   1536
#define CHUNK 64
#define NCH  32

#define THETA_SCALE 7.66990393942820573e-4f  // (pi/2)/2048

// ---------------- scratch (device globals; no allocs allowed) ----------------
__device__ float g_qkv[LSEQ * E3];
__device__ float g_ckv[HEADS * NCH * 2 * DDIM * DDIM];
__device__ float g_ck [HEADS * NCH * 2 * DDIM];
__device__ float g_pkv[HEADS * NCH * 2 * DDIM * DDIM];
__device__ float g_pk [HEADS * NCH * 2 * DDIM];

// fp16 buffers (pure fp16 GEMM scheme)
__device__ __half g_xh[LSEQ * EDIM];
__device__ __half g_wqh[E3 * EDIM];   // Wqkv^T  [1536][512]
__device__ __half g_woh[EDIM * EDIM]; // Wout^T  [512][512]
__device__ __half g_ah[LSEQ * EDIM];  // attention out (fp16)

// ---------------- low-level helpers ----------------
__device__ __forceinline__ uint32_t smem_u32(const void* p) {
    uint32_t a;
    asm("{ .reg .u64 t; cvta.to.shared.u64 t, %1; cvt.u32.u64 %0, t; }"
        : "=r"(a) : "l"(p));
    return a;
}
#define CP_ASYNC16(dst, src) \
    asm volatile("cp.async.cg.shared.global [%0], [%1], 16;" :: "r"(dst), "l"(src))
#define CP_COMMIT() asm volatile("cp.async.commit_group;" ::: "memory")
#define CP_WAIT0()  asm volatile("cp.async.wait_group 0;" ::: "memory")
#define CP_WAIT1()  asm volatile("cp.async.wait_group 1;" ::: "memory")
#define CP_WAIT2()  asm volatile("cp.async.wait_group 2;" ::: "memory")

__device__ __forceinline__ void ldmx4(uint32_t* r, uint32_t addr) {
    asm volatile("ldmatrix.sync.aligned.m8n8.x4.shared.b16 {%0,%1,%2,%3}, [%4];"
                 : "=r"(r[0]), "=r"(r[1]), "=r"(r[2]), "=r"(r[3]) : "r"(addr));
}
__device__ __forceinline__ void mma16816(float* c, const uint32_t* a, const uint32_t* b) {
    asm volatile(
        "mma.sync.aligned.m16n8k16.row.col.f32.f16.f16.f32 "
        "{%0,%1,%2,%3}, {%4,%5,%6,%7}, {%8,%9}, {%0,%1,%2,%3};"
        : "+f"(c[0]), "+f"(c[1]), "+f"(c[2]), "+f"(c[3])
        : "r"(a[0]), "r"(a[1]), "r"(a[2]), "r"(a[3]), "r"(b[0]), "r"(b[1]));
}

// ---------------- fused split kernel: x fp16 + both weight transposes ------
__device__ __forceinline__ void transpose_half_tile(
    const float* __restrict__ W, __half* __restrict__ hiT,
    int K, int N, int bx, int by, float (*t)[33]) {
    const int tx = threadIdx.x & 31, ty = threadIdx.x >> 5;  // (32, 8)
    const int n0 = bx * 32, k0 = by * 32;
    #pragma unroll
    for (int j = 0; j < 4; j++)
        t[ty + 8 * j][tx] = W[(size_t)(k0 + ty + 8 * j) * N + n0 + tx];
    __syncthreads();
    #pragma unroll
    for (int j = 0; j < 4; j++)
        hiT[(size_t)(n0 + ty + 8 * j) * K + k0 + tx] = __float2half(t[tx][ty + 8 * j]);
}

__global__ __launch_bounds__(256)
void split_all_kernel(const float* __restrict__ x,
                      const float* __restrict__ Wqkv,
                      const float* __restrict__ Wout) {
    __shared__ float t[32][33];
    const int b = blockIdx.x;
    if (b < 1024) {
        int i = b * 1024 + threadIdx.x * 4;
        float4 a4 = *reinterpret_cast<const float4*>(&x[i]);
        __half hv[4] = {__float2half(a4.x), __float2half(a4.y),
                        __float2half(a4.z), __float2half(a4.w)};
        *reinterpret_cast<uint2*>(&g_xh[i]) = *reinterpret_cast<uint2*>(hv);
    } else if (b < 1024 + 768) {
        int tt = b - 1024;                 // Wqkv: K=512, N=1536 -> 48 x 16 tiles
        transpose_half_tile(Wqkv, g_wqh, EDIM, E3, tt % 48, tt / 48, t);
    } else {
        int tt = b - 1024 - 768;           // Wout: K=512, N=512 -> 16 x 16 tiles
        transpose_half_tile(Wout, g_woh, EDIM, EDIM, tt % 16, tt / 16, t);
    }
}

// ---------------- mma.sync fp16 GEMM: C[M,N] = A @ Bt^T + bias --------------
// Pure fp16 A and B, fp32 accum. BN = 128 fixed. 8 warps as 2(M) x 4(N).
// K-chunk 32, 3-stage cp.async pipeline, 4 CTAs/SM.
#define KC 32
#define AST 40   // smem row stride in fp16 elems

template<int BM>
__global__ __launch_bounds__(256, 4)
void mma_gemm_kernel(const __half* __restrict__ Ah,
                     const __half* __restrict__ Bh,
                     const float* __restrict__ bias, float* __restrict__ C,
                     int N, int K) {
    constexpr int MI = BM / 32;
    constexpr int TILE_A = BM * AST;
    constexpr int TILE_B = 128 * AST;
    constexpr int BUF_E  = TILE_A + TILE_B;

    extern __shared__ __half smem[];
    const int tid = threadIdx.x;
    const int wid = tid >> 5, lane = tid & 31;
    const int bn0 = blockIdx.x * 128, bm0 = blockIdx.y * BM;
    const int wm = (wid & 1) * (BM / 2);
    const int wn = (wid >> 1) * 32;

    const uint32_t smb = smem_u32(smem);
    const int NCHK = K / KC;

    float acc[MI][4][4];
    #pragma unroll
    for (int mi = 0; mi < MI; mi++)
        #pragma unroll
        for (int nj = 0; nj < 4; nj++)
            #pragma unroll
            for (int r = 0; r < 4; r++) acc[mi][nj][r] = 0.f;

    const __half* srcs[2] = {Ah, Bh};
    const int  srow[2] = {bm0, bn0};
    const int  titem[2] = {BM * KC / 8, 128 * KC / 8};
    const uint32_t toff[2] = {0u, (uint32_t)TILE_A};

    auto load_chunk = [&](int b, int k0) {
        #pragma unroll
        for (int t = 0; t < 2; t++) {
            const __half* s = srcs[t];
            uint32_t dbase = smb + (uint32_t)(b * BUF_E + toff[t]) * 2u;
            const int nit = titem[t];
            for (int item = tid; item < nit; item += 256) {
                int row = item >> 2, sub = item & 3;
                uint32_t d = dbase + (uint32_t)(row * AST + sub * 8) * 2u;
                const void* g = (const void*)(s + (size_t)(srow[t] + row) * K + k0 + sub * 8);
                CP_ASYNC16(d, g);
            }
        }
        CP_COMMIT();
    };

    load_chunk(0, 0);
    load_chunk(1, KC);

    for (int c = 0; c < NCHK; c++) {
        const int b = c % 3;
        if (c + 2 < NCHK) load_chunk((c + 2) % 3, (c + 2) * KC);
        if (c + 2 < NCHK)      CP_WAIT2();
        else if (c + 1 < NCHK) CP_WAIT1();
        else                   CP_WAIT0();
        __syncthreads();

        const uint32_t aB = smb + (uint32_t)(b * BUF_E) * 2u;
        const uint32_t bB = aB + (uint32_t)TILE_A * 2u;

        #pragma unroll
        for (int ks = 0; ks < KC; ks += 16) {
            const int arow = wm + (lane & 15);
            const int acol = ks + ((lane >> 4) << 3);
            uint32_t ah[MI][4];
            #pragma unroll
            for (int mi = 0; mi < MI; mi++) {
                uint32_t off = (uint32_t)((arow + mi * 16) * AST + acol) * 2u;
                ldmx4(ah[mi], aB + off);
            }
            const int brow = wn + (lane & 7) + ((lane & 16) ? 8 : 0);
            const int bcol = ks + ((lane & 8) ? 8 : 0);
            uint32_t bh[2][4];
            #pragma unroll
            for (int ni = 0; ni < 2; ni++) {
                uint32_t off = (uint32_t)((brow + ni * 16) * AST + bcol) * 2u;
                ldmx4(bh[ni], bB + off);
            }
            #pragma unroll
            for (int mi = 0; mi < MI; mi++) {
                #pragma unroll
                for (int nj = 0; nj < 4; nj++) {
                    const uint32_t* ph = &bh[nj >> 1][(nj & 1) * 2];
                    mma16816(acc[mi][nj], ah[mi], ph);
                }
            }
        }
        __syncthreads();
    }

    const int r0 = bm0 + wm + (lane >> 2);
    const int c0 = bn0 + wn + (lane & 3) * 2;
    #pragma unroll
    for (int mi = 0; mi < MI; mi++) {
        #pragma unroll
        for (int nj = 0; nj < 4; nj++) {
            int row = r0 + mi * 16;
            int col = c0 + nj * 8;
            float b0 = bias[col], b1 = bias[col + 1];
            float2 v0 = make_float2(acc[mi][nj][0] + b0, acc[mi][nj][1] + b1);
            float2 v1 = make_float2(acc[mi][nj][2] + b0, acc[mi][nj][3] + b1);
            *reinterpret_cast<float2*>(&C[(size_t)row * N + col]) = v0;
            *reinterpret_cast<float2*>(&C[(size_t)(row + 8) * N + col]) = v1;
        }
    }
}

// smem bytes: 3 buffers x (BM + 128) * AST * 2 bytes
#define GSMEM(BM) ((BM + 128) * AST * 6)

// ---------------------------------------------------------------------------
// chunk_sum: per-chunk (C=64) KV / K sums. grid (NCH, HEADS) = 256 blocks.
// ---------------------------------------------------------------------------
__global__ __launch_bounds__(256)
void chunk_sum_kernel() {
    extern __shared__ float smf[];
    float* rk = smf;                 // [64][64]
    float* vv = rk + CHUNK * DDIM;   // [64][64]
    float* cw = vv + CHUNK * DDIM;   // [64]
    float* sw = cw + CHUNK;          // [64]

    const int c = blockIdx.x, h = blockIdx.y, tid = threadIdx.x;

    for (int t = tid; t < CHUNK * DDIM; t += 256) {
        int i = t >> 6, d = t & 63;
        const float* row = g_qkv + (size_t)(c * CHUNK + i) * E3 + h * DDIM;
        rk[t] = fmaxf(row[EDIM + d], 0.f);
        vv[t] = row[2 * EDIM + d];
    }
    if (tid < CHUNK) {
        float th = (float)(c * CHUNK + tid) * THETA_SCALE;
        cw[tid] = cosf(th);
        sw[tid] = sinf(th);
    }
    __syncthreads();

    const int d  = tid & 63;
    const int eg = (tid >> 6) << 4;
    float aC[16], aS[16];
    #pragma unroll
    for (int e = 0; e < 16; e++) { aC[e] = 0.f; aS[e] = 0.f; }

    for (int i = 0; i < CHUNK; i++) {
        float kd = rk[i * DDIM + d];
        float kc = kd * cw[i];
        float ks = kd * sw[i];
        const float4* vp = reinterpret_cast<const float4*>(&vv[i * DDIM + eg]);
        #pragma unroll
        for (int e4 = 0; e4 < 4; e4++) {
            float4 v4 = vp[e4];
            aC[e4 * 4 + 0] += kc * v4.x; aC[e4 * 4 + 1] += kc * v4.y;
            aC[e4 * 4 + 2] += kc * v4.z; aC[e4 * 4 + 3] += kc * v4.w;
            aS[e4 * 4 + 0] += ks * v4.x; aS[e4 * 4 + 1] += ks * v4.y;
            aS[e4 * 4 + 2] += ks * v4.z; aS[e4 * 4 + 3] += ks * v4.w;
        }
    }

    size_t base = (size_t)(h * NCH + c) * 2 * DDIM * DDIM;
    #pragma unroll
    for (int e = 0; e < 16; e++) {
        g_ckv[base + d * DDIM + eg + e]               = aC[e];
        g_ckv[base + DDIM * DDIM + d * DDIM + eg + e] = aS[e];
    }

    if (tid < DDIM) {
        float sc = 0.f, ss = 0.f;
        for (int i = 0; i < CHUNK; i++) {
            float kd = rk[i * DDIM + tid];
            sc += kd * cw[i];
            ss += kd * sw[i];
        }
        size_t kb = (size_t)(h * NCH + c) * 2 * DDIM;
        g_ck[kb + tid]        = sc;
        g_ck[kb + DDIM + tid] = ss;
    }
}

// ---------------------------------------------------------------------------
// scan: exclusive prefix over 32 chunks. grid 256 x 256, one thread per lane.
// ---------------------------------------------------------------------------
__global__ __launch_bounds__(256)
void scan_kernel() {
    const int h = blockIdx.x >> 5;
    const int idx = (blockIdx.x & 31) * 256 + threadIdx.x;  // 0..8191
    const int KVSZ = 2 * DDIM * DDIM;  // 8192

    float v[NCH];
    #pragma unroll
    for (int c = 0; c < NCH; c++)
        v[c] = g_ckv[(size_t)(h * NCH + c) * KVSZ + idx];
    float run = 0.f;
    #pragma unroll
    for (int c = 0; c < NCH; c++) {
        g_pkv[(size_t)(h * NCH + c) * KVSZ + idx] = run;
        run += v[c];
    }

    if ((blockIdx.x & 31) == 0 && threadIdx.x < 2 * DDIM) {
        const int t = threadIdx.x;
        const int KSZ = 2 * DDIM;
        float w[NCH];
        #pragma unroll
        for (int c = 0; c < NCH; c++)
            w[c] = g_ck[(size_t)(h * NCH + c) * KSZ + t];
        float r2 = 0.f;
        #pragma unroll
        for (int c = 0; c < NCH; c++) {
            g_pk[(size_t)(h * NCH + c) * KSZ + t] = r2;
            r2 += w[c];
        }
    }
}

// ---------------------------------------------------------------------------
// chunk_out (C=64): register-tiled, predicated-causal, fp16 output.
// grid (NCH, HEADS) = 256 blocks, 256 threads. Parallel nrm (4 thr/row).
// ---------------------------------------------------------------------------
#define RQT_STRIDE 68
#define S_STRIDE   66

__global__ __launch_bounds__(256)
void chunk_out_kernel() {
    extern __shared__ float smf[];
    float* rqT = smf;                       // [64][68]
    float* rkT = rqT + DDIM * RQT_STRIDE;   // [64][68]
    float* vv  = rkT + DDIM * RQT_STRIDE;   // [64][64]
    float* S   = vv + CHUNK * DDIM;         // [64][66]
    float* KVc = S + CHUNK * S_STRIDE;      // [64][64]
    float* KVs = KVc + DDIM * DDIM;         // [64][64]
    float* K0c = KVs + DDIM * DDIM;         // [64]
    float* K0s = K0c + DDIM;                // [64]
    float* cw  = K0s + DDIM;                // [64]
    float* sw  = cw + CHUNK;                // [64]
    float* nrm = sw + CHUNK;                // [64]
    float* nrm4 = nrm + CHUNK;              // [4][64]

    const int c = blockIdx.x, h = blockIdx.y, tid = threadIdx.x;

    for (int t = tid; t < CHUNK * DDIM; t += 256) {
        int i = t >> 6, d = t & 63;
        const float* row = g_qkv + (size_t)(c * CHUNK + i) * E3 + h * DDIM;
        rqT[d * RQT_STRIDE + i] = fmaxf(row[d], 0.f);
        rkT[d * RQT_STRIDE + i] = fmaxf(row[EDIM + d], 0.f);
        vv[i * DDIM + d]        = row[2 * EDIM + d];
    }
    if (tid < CHUNK) {
        float th = (float)(c * CHUNK + tid) * THETA_SCALE;
        cw[tid] = cosf(th);
        sw[tid] = sinf(th);
    }
    {
        const float* base = g_pkv + (size_t)(h * NCH + c) * 2 * DDIM * DDIM;
        for (int t = tid; t < 2 * DDIM * DDIM; t += 256) {
            if (t < DDIM * DDIM) KVc[t] = base[t];
            else                 KVs[t - DDIM * DDIM] = base[t];
        }
        const float* kb = g_pk + (size_t)(h * NCH + c) * 2 * DDIM;
        if (tid < 2 * DDIM) {
            if (tid < DDIM) K0c[tid] = kb[tid];
            else            K0s[tid - DDIM] = kb[tid];
        }
    }
    __syncthreads();

    // ---- phase 1: S[i][j] (j<=i), 4x4 tiles on a 16x16 thread grid
    {
        const int ti = tid >> 4, tj = tid & 15;
        const int i0 = ti * 4, j0 = tj * 4;
        if (j0 <= i0 + 3) {
            float acc[4][4];
            #pragma unroll
            for (int r = 0; r < 4; r++)
                #pragma unroll
                for (int q = 0; q < 4; q++) acc[r][q] = 0.f;

            for (int d = 0; d < DDIM; d++) {
                float4 a4 = *reinterpret_cast<const float4*>(&rqT[d * RQT_STRIDE + i0]);
                float4 b4 = *reinterpret_cast<const float4*>(&rkT[d * RQT_STRIDE + j0]);
                float a[4] = {a4.x, a4.y, a4.z, a4.w};
                float b[4] = {b4.x, b4.y, b4.z, b4.w};
                #pragma unroll
                for (int r = 0; r < 4; r++)
                    #pragma unroll
                    for (int q = 0; q < 4; q++)
                        acc[r][q] += a[r] * b[q];
            }
            #pragma unroll
            for (int r = 0; r < 4; r++) {
                int i = i0 + r;
                float ci = cw[i], si = sw[i];
                #pragma unroll
                for (int q = 0; q < 4; q++) {
                    int j = j0 + q;
                    if (j <= i)
                        S[i * S_STRIDE + j] = acc[r][q] * (ci * cw[j] + si * sw[j]);
                }
            }
        }
    }
    __syncthreads();

    // ---- phase 2: nrm, 4 threads per row
    {
        const int i2 = tid & 63, qd = tid >> 6;
        float dc = 0.f, ds = 0.f;
        #pragma unroll
        for (int dd = 0; dd < 16; dd++) {
            int d = qd * 16 + dd;
            float q = rqT[d * RQT_STRIDE + i2];
            dc += q * K0c[d];
            ds += q * K0s[d];
        }
        float part = cw[i2] * dc + sw[i2] * ds;
        int jbeg = qd * 16;
        int jend = (i2 < jbeg + 15) ? i2 : (jbeg + 15);
        for (int j = jbeg; j <= jend; j++) part += S[i2 * S_STRIDE + j];
        nrm4[qd * 64 + i2] = part;
    }
    __syncthreads();
    if (tid < CHUNK)
        nrm[tid] = nrm4[tid] + nrm4[64 + tid] + nrm4[128 + tid] + nrm4[192 + tid];
    __syncthreads();

    // ---- phase 3: 2 rows x 8 cols per thread
    const int tx = tid & 7, ty = tid >> 3;
    const int e0 = tx * 8, i0 = ty * 2;

    float tC[2][8], tS[2][8], tI[2][8];
    #pragma unroll
    for (int r = 0; r < 2; r++)
        #pragma unroll
        for (int e = 0; e < 8; e++) { tC[r][e] = 0.f; tS[r][e] = 0.f; tI[r][e] = 0.f; }

    for (int d = 0; d < DDIM; d++) {
        float2 q2 = *reinterpret_cast<const float2*>(&rqT[d * RQT_STRIDE + i0]);
        float qr[2] = {q2.x, q2.y};
        float4 c0 = *reinterpret_cast<const float4*>(&KVc[d * DDIM + e0]);
        float4 c1 = *reinterpret_cast<const float4*>(&KVc[d * DDIM + e0 + 4]);
        float4 s0 = *reinterpret_cast<const float4*>(&KVs[d * DDIM + e0]);
        float4 s1 = *reinterpret_cast<const float4*>(&KVs[d * DDIM + e0 + 4]);
        float cv[8] = {c0.x, c0.y, c0.z, c0.w, c1.x, c1.y, c1.z, c1.w};
        float sv[8] = {s0.x, s0.y, s0.z, s0.w, s1.x, s1.y, s1.z, s1.w};
        #pragma unroll
        for (int r = 0; r < 2; r++)
            #pragma unroll
            for (int e = 0; e < 8; e++) {
                tC[r][e] += qr[r] * cv[e];
                tS[r][e] += qr[r] * sv[e];
            }
    }

    for (int j = 0; j <= i0; j++) {
        float sr[2];
        #pragma unroll
        for (int r = 0; r < 2; r++) sr[r] = S[(i0 + r) * S_STRIDE + j];
        float4 v0 = *reinterpret_cast<const float4*>(&vv[j * DDIM + e0]);
        float4 v1 = *reinterpret_cast<const float4*>(&vv[j * DDIM + e0 + 4]);
        float ve[8] = {v0.x, v0.y, v0.z, v0.w, v1.x, v1.y, v1.z, v1.w};
        #pragma unroll
        for (int r = 0; r < 2; r++)
            #pragma unroll
            for (int e = 0; e < 8; e++)
                tI[r][e] += sr[r] * ve[e];
    }
    {   // tail j = i0+1, valid only for r=1
        const int j = i0 + 1;
        float s1 = S[(i0 + 1) * S_STRIDE + j];
        float4 v0 = *reinterpret_cast<const float4*>(&vv[j * DDIM + e0]);
        float4 v1 = *reinterpret_cast<const float4*>(&vv[j * DDIM + e0 + 4]);
        float ve[8] = {v0.x, v0.y, v0.z, v0.w, v1.x, v1.y, v1.z, v1.w};
        #pragma unroll
        for (int e = 0; e < 8; e++)
            tI[1][e] += s1 * ve[e];
    }

    // ---- epilogue: combine, normalize, fp16 round, store
    #pragma unroll
    for (int r = 0; r < 2; r++) {
        const int i = i0 + r;
        float ci = cw[i], si = sw[i];
        float inv = 1.0f / (nrm[i] + 1e-6f);
        uint32_t ph[4];
        #pragma unroll
        for (int e2 = 0; e2 < 4; e2++) {
            float v0 = (ci * tC[r][e2 * 2 + 0] + si * tS[r][e2 * 2 + 0] + tI[r][e2 * 2 + 0]) * inv;
            float v1 = (ci * tC[r][e2 * 2 + 1] + si * tS[r][e2 * 2 + 1] + tI[r][e2 * 2 + 1]) * inv;
            __half h0 = __float2half(v0);
            __half h1 = __float2half(v1);
            ph[e2] = (uint32_t)__half_as_ushort(h0) |
                     ((uint32_t)__half_as_ushort(h1) << 16);
        }
        size_t base = (size_t)(c * CHUNK + i) * EDIM + h * DDIM + e0;
        *reinterpret_cast<uint4*>(&g_ah[base]) = make_uint4(ph[0], ph[1], ph[2], ph[3]);
    }
}

// ---------------------------------------------------------------------------

static const int SMEM_SUM = (2 * CHUNK * DDIM + 2 * CHUNK) * (int)sizeof(float);
static const int SMEM_OUT = (2 * DDIM * RQT_STRIDE + CHUNK * DDIM + CHUNK * S_STRIDE +
                             2 * DDIM * DDIM + 2 * DDIM + 3 * CHUNK + 4 * CHUNK) * (int)sizeof(float);

extern "C" void kernel_launch(void* const* d_in, const int* in_sizes, int n_in,
                              void* d_out, int out_size) {
    (void)in_sizes; (void)n_in; (void)out_size;
    const float* x    = (const float*)d_in[0];
    const float* Wqkv = (const float*)d_in[1];
    const float* bqkv = (const float*)d_in[2];
    const float* Wout = (const float*)d_in[3];
    const float* bout = (const float*)d_in[4];
    float* out = (float*)d_out;

    float* qkv_ptr;
    cudaGetSymbolAddress((void**)&qkv_ptr, g_qkv);
    __half *xh, *wqh, *woh, *ah;
    cudaGetSymbolAddress((void**)&xh, g_xh);
    cudaGetSymbolAddress((void**)&wqh, g_wqh);
    cudaGetSymbolAddress((void**)&woh, g_woh);
    cudaGetSymbolAddress((void**)&ah, g_ah);

    cudaFuncSetAttribute(chunk_sum_kernel,
                         cudaFuncAttributeMaxDynamicSharedMemorySize, SMEM_SUM);
    cudaFuncSetAttribute(chunk_out_kernel,
                         cudaFuncAttributeMaxDynamicSharedMemorySize, SMEM_OUT);
    cudaFuncSetAttribute((const void*)mma_gemm_kernel<64>,
                         cudaFuncAttributeMaxDynamicSharedMemorySize, GSMEM(64));
    cudaFuncSetAttribute((const void*)mma_gemm_kernel<32>,
                         cudaFuncAttributeMaxDynamicSharedMemorySize, GSMEM(32));

    // fp16 conversions: x + Wqkv^T + Wout^T, one launch
    split_all_kernel<<<1024 + 768 + 256, 256>>>(x, Wqkv, Wout);

    // 1) QKV GEMM: 64x128 tiles -> grid 384, 4 CTAs/SM, 3-stage pipeline
    mma_gemm_kernel<64><<<dim3(E3 / 128, LSEQ / 64), 256, GSMEM(64)>>>(
        xh, wqh, bqkv, qkv_ptr, E3, EDIM);

    // 2) Chunked cosformer attention
    chunk_sum_kernel<<<dim3(NCH, HEADS), 256, SMEM_SUM>>>();
    scan_kernel<<<256, 256>>>();
    chunk_out_kernel<<<dim3(NCH, HEADS), 256, SMEM_OUT>>>();

    // 3) Output GEMM: 32x128 tiles -> grid 256, 3-stage pipeline
    mma_gemm_kernel<32><<<dim3(EDIM / 128, LSEQ / 32), 256, GSMEM(32)>>>(
        ah, woh, bout, out, EDIM, EDIM);
}

// round 16
// speedup vs baseline: 1.2073x; 1.0706x over previous
#include <cuda_runtime.h>
#include <cuda_fp16.h>
#include <cstdint>
#include <cstddef>

// Problem constants
#define LSEQ 2048
#define EDIM 512
#define HEADS 8
#define DDIM 64
#define E3   1536
#define CHUNK 64
#define NCH  32

#define THETA_SCALE 7.66990393942820573e-4f  // (pi/2)/2048

// ---------------- scratch (device globals; no allocs allowed) ----------------
__device__ __half g_qkvh[LSEQ * E3];   // fp16 QKV, relu pre-applied to Q,K cols
__device__ float g_ckv[HEADS * NCH * 2 * DDIM * DDIM];
__device__ float g_ck [HEADS * NCH * 2 * DDIM];
__device__ float g_pkv[HEADS * NCH * 2 * DDIM * DDIM];
__device__ float g_pk [HEADS * NCH * 2 * DDIM];

// fp16 buffers
__device__ __half g_xh[LSEQ * EDIM];
__device__ __half g_wqh[E3 * EDIM];   // Wqkv^T  [1536][512]
__device__ __half g_woh[EDIM * EDIM]; // Wout^T  [512][512]
__device__ __half g_ah[LSEQ * EDIM];  // attention out (fp16)

// ---------------- low-level helpers ----------------
__device__ __forceinline__ uint32_t smem_u32(const void* p) {
    uint32_t a;
    asm("{ .reg .u64 t; cvta.to.shared.u64 t, %1; cvt.u32.u64 %0, t; }"
        : "=r"(a) : "l"(p));
    return a;
}
#define CP_ASYNC16(dst, src) \
    asm volatile("cp.async.cg.shared.global [%0], [%1], 16;" :: "r"(dst), "l"(src))
#define CP_COMMIT() asm volatile("cp.async.commit_group;" ::: "memory")
#define CP_WAIT0()  asm volatile("cp.async.wait_group 0;" ::: "memory")
#define CP_WAIT1()  asm volatile("cp.async.wait_group 1;" ::: "memory")
#define CP_WAIT2()  asm volatile("cp.async.wait_group 2;" ::: "memory")

__device__ __forceinline__ void ldmx4(uint32_t* r, uint32_t addr) {
    asm volatile("ldmatrix.sync.aligned.m8n8.x4.shared.b16 {%0,%1,%2,%3}, [%4];"
                 : "=r"(r[0]), "=r"(r[1]), "=r"(r[2]), "=r"(r[3]) : "r"(addr));
}
__device__ __forceinline__ void mma16816(float* c, const uint32_t* a, const uint32_t* b) {
    asm volatile(
        "mma.sync.aligned.m16n8k16.row.col.f32.f16.f16.f32 "
        "{%0,%1,%2,%3}, {%4,%5,%6,%7}, {%8,%9}, {%0,%1,%2,%3};"
        : "+f"(c[0]), "+f"(c[1]), "+f"(c[2]), "+f"(c[3])
        : "r"(a[0]), "r"(a[1]), "r"(a[2]), "r"(a[3]), "r"(b[0]), "r"(b[1]));
}

// ---------------- fused split kernel: x fp16 + both weight transposes ------
__device__ __forceinline__ void transpose_half_tile(
    const float* __restrict__ W, __half* __restrict__ hiT,
    int K, int N, int bx, int by, float (*t)[33]) {
    const int tx = threadIdx.x & 31, ty = threadIdx.x >> 5;  // (32, 8)
    const int n0 = bx * 32, k0 = by * 32;
    #pragma unroll
    for (int j = 0; j < 4; j++)
        t[ty + 8 * j][tx] = W[(size_t)(k0 + ty + 8 * j) * N + n0 + tx];
    __syncthreads();
    #pragma unroll
    for (int j = 0; j < 4; j++)
        hiT[(size_t)(n0 + ty + 8 * j) * K + k0 + tx] = __float2half(t[tx][ty + 8 * j]);
}

__global__ __launch_bounds__(256)
void split_all_kernel(const float* __restrict__ x,
                      const float* __restrict__ Wqkv,
                      const float* __restrict__ Wout) {
    __shared__ float t[32][33];
    const int b = blockIdx.x;
    if (b < 1024) {
        int i = b * 1024 + threadIdx.x * 4;
        float4 a4 = *reinterpret_cast<const float4*>(&x[i]);
        __half hv[4] = {__float2half(a4.x), __float2half(a4.y),
                        __float2half(a4.z), __float2half(a4.w)};
        *reinterpret_cast<uint2*>(&g_xh[i]) = *reinterpret_cast<uint2*>(hv);
    } else if (b < 1024 + 768) {
        int tt = b - 1024;                 // Wqkv: K=512, N=1536 -> 48 x 16 tiles
        transpose_half_tile(Wqkv, g_wqh, EDIM, E3, tt % 48, tt / 48, t);
    } else {
        int tt = b - 1024 - 768;           // Wout: K=512, N=512 -> 16 x 16 tiles
        transpose_half_tile(Wout, g_woh, EDIM, EDIM, tt % 16, tt / 16, t);
    }
}

// ---------------- mma.sync fp16 GEMM: C[M,N] = A @ Bt^T + bias --------------
// Pure fp16 A and B, fp32 accum. BN = 128 fixed. 8 warps as 2(M) x 4(N).
// K-chunk 32, 3-stage cp.async pipeline, 4 CTAs/SM.
// HOUT=true: fp16 output with relu applied to cols < 2*EDIM (Q,K region).
#define KC 32
#define AST 40   // smem row stride in fp16 elems

template<int BM, bool HOUT>
__global__ __launch_bounds__(256, 4)
void mma_gemm_kernel(const __half* __restrict__ Ah,
                     const __half* __restrict__ Bh,
                     const float* __restrict__ bias, void* __restrict__ Cv,
                     int N, int K) {
    constexpr int MI = BM / 32;
    constexpr int TILE_A = BM * AST;
    constexpr int TILE_B = 128 * AST;
    constexpr int BUF_E  = TILE_A + TILE_B;

    extern __shared__ __half smem[];
    const int tid = threadIdx.x;
    const int wid = tid >> 5, lane = tid & 31;
    const int bn0 = blockIdx.x * 128, bm0 = blockIdx.y * BM;
    const int wm = (wid & 1) * (BM / 2);
    const int wn = (wid >> 1) * 32;

    const uint32_t smb = smem_u32(smem);
    const int NCHK = K / KC;

    float acc[MI][4][4];
    #pragma unroll
    for (int mi = 0; mi < MI; mi++)
        #pragma unroll
        for (int nj = 0; nj < 4; nj++)
            #pragma unroll
            for (int r = 0; r < 4; r++) acc[mi][nj][r] = 0.f;

    const __half* srcs[2] = {Ah, Bh};
    const int  srow[2] = {bm0, bn0};
    const int  titem[2] = {BM * KC / 8, 128 * KC / 8};
    const uint32_t toff[2] = {0u, (uint32_t)TILE_A};

    auto load_chunk = [&](int b, int k0) {
        #pragma unroll
        for (int t = 0; t < 2; t++) {
            const __half* s = srcs[t];
            uint32_t dbase = smb + (uint32_t)(b * BUF_E + toff[t]) * 2u;
            const int nit = titem[t];
            for (int item = tid; item < nit; item += 256) {
                int row = item >> 2, sub = item & 3;
                uint32_t d = dbase + (uint32_t)(row * AST + sub * 8) * 2u;
                const void* g = (const void*)(s + (size_t)(srow[t] + row) * K + k0 + sub * 8);
                CP_ASYNC16(d, g);
            }
        }
        CP_COMMIT();
    };

    load_chunk(0, 0);
    load_chunk(1, KC);

    for (int c = 0; c < NCHK; c++) {
        const int b = c % 3;
        if (c + 2 < NCHK) load_chunk((c + 2) % 3, (c + 2) * KC);
        if (c + 2 < NCHK)      CP_WAIT2();
        else if (c + 1 < NCHK) CP_WAIT1();
        else                   CP_WAIT0();
        __syncthreads();

        const uint32_t aB = smb + (uint32_t)(b * BUF_E) * 2u;
        const uint32_t bB = aB + (uint32_t)TILE_A * 2u;

        #pragma unroll
        for (int ks = 0; ks < KC; ks += 16) {
            const int arow = wm + (lane & 15);
            const int acol = ks + ((lane >> 4) << 3);
            uint32_t ah[MI][4];
            #pragma unroll
            for (int mi = 0; mi < MI; mi++) {
                uint32_t off = (uint32_t)((arow + mi * 16) * AST + acol) * 2u;
                ldmx4(ah[mi], aB + off);
            }
            const int brow = wn + (lane & 7) + ((lane & 16) ? 8 : 0);
            const int bcol = ks + ((lane & 8) ? 8 : 0);
            uint32_t bh[2][4];
            #pragma unroll
            for (int ni = 0; ni < 2; ni++) {
                uint32_t off = (uint32_t)((brow + ni * 16) * AST + bcol) * 2u;
                ldmx4(bh[ni], bB + off);
            }
            #pragma unroll
            for (int mi = 0; mi < MI; mi++) {
                #pragma unroll
                for (int nj = 0; nj < 4; nj++) {
                    const uint32_t* ph = &bh[nj >> 1][(nj & 1) * 2];
                    mma16816(acc[mi][nj], ah[mi], ph);
                }
            }
        }
        __syncthreads();
    }

    const int r0 = bm0 + wm + (lane >> 2);
    const int c0 = bn0 + wn + (lane & 3) * 2;
    #pragma unroll
    for (int mi = 0; mi < MI; mi++) {
        #pragma unroll
        for (int nj = 0; nj < 4; nj++) {
            int row = r0 + mi * 16;
            int col = c0 + nj * 8;
            float b0 = bias[col], b1 = bias[col + 1];
            float v00 = acc[mi][nj][0] + b0, v01 = acc[mi][nj][1] + b1;
            float v10 = acc[mi][nj][2] + b0, v11 = acc[mi][nj][3] + b1;
            if constexpr (HOUT) {
                __half* Ch = (__half*)Cv;
                if (col < 2 * EDIM) {  // Q,K region: fuse relu
                    v00 = fmaxf(v00, 0.f); v01 = fmaxf(v01, 0.f);
                    v10 = fmaxf(v10, 0.f); v11 = fmaxf(v11, 0.f);
                }
                *reinterpret_cast<__half2*>(&Ch[(size_t)row * N + col]) =
                    __floats2half2_rn(v00, v01);
                *reinterpret_cast<__half2*>(&Ch[(size_t)(row + 8) * N + col]) =
                    __floats2half2_rn(v10, v11);
            } else {
                float* Cf = (float*)Cv;
                *reinterpret_cast<float2*>(&Cf[(size_t)row * N + col]) = make_float2(v00, v01);
                *reinterpret_cast<float2*>(&Cf[(size_t)(row + 8) * N + col]) = make_float2(v10, v11);
            }
        }
    }
}

// smem bytes: 3 buffers x (BM + 128) * AST * 2 bytes
#define GSMEM(BM) ((BM + 128) * AST * 6)

// ---------------------------------------------------------------------------
// chunk_sum: per-chunk (C=64) KV / K sums. grid (NCH, HEADS) = 256 blocks.
// Reads fp16 g_qkvh (relu pre-applied to K).
// ---------------------------------------------------------------------------
__global__ __launch_bounds__(256)
void chunk_sum_kernel() {
    extern __shared__ float smf[];
    float* rk = smf;                 // [64][64]
    float* vv = rk + CHUNK * DDIM;   // [64][64]
    float* cw = vv + CHUNK * DDIM;   // [64]
    float* sw = cw + CHUNK;          // [64]

    const int c = blockIdx.x, h = blockIdx.y, tid = threadIdx.x;

    // 2048 half2 pairs for each of K and V
    for (int t = tid; t < CHUNK * DDIM / 2; t += 256) {
        int i = t >> 5, d2 = t & 31;         // d = d2*2
        const __half* row = g_qkvh + (size_t)(c * CHUNK + i) * E3 + h * DDIM;
        __half2 k2 = *reinterpret_cast<const __half2*>(&row[EDIM + d2 * 2]);
        __half2 v2 = *reinterpret_cast<const __half2*>(&row[2 * EDIM + d2 * 2]);
        float2 kf = __half22float2(k2);
        float2 vf = __half22float2(v2);
        rk[i * DDIM + d2 * 2]     = kf.x;
        rk[i * DDIM + d2 * 2 + 1] = kf.y;
        vv[i * DDIM + d2 * 2]     = vf.x;
        vv[i * DDIM + d2 * 2 + 1] = vf.y;
    }
    if (tid < CHUNK) {
        float th = (float)(c * CHUNK + tid) * THETA_SCALE;
        cw[tid] = cosf(th);
        sw[tid] = sinf(th);
    }
    __syncthreads();

    const int d  = tid & 63;
    const int eg = (tid >> 6) << 4;
    float aC[16], aS[16];
    #pragma unroll
    for (int e = 0; e < 16; e++) { aC[e] = 0.f; aS[e] = 0.f; }

    for (int i = 0; i < CHUNK; i++) {
        float kd = rk[i * DDIM + d];
        float kc = kd * cw[i];
        float ks = kd * sw[i];
        const float4* vp = reinterpret_cast<const float4*>(&vv[i * DDIM + eg]);
        #pragma unroll
        for (int e4 = 0; e4 < 4; e4++) {
            float4 v4 = vp[e4];
            aC[e4 * 4 + 0] += kc * v4.x; aC[e4 * 4 + 1] += kc * v4.y;
            aC[e4 * 4 + 2] += kc * v4.z; aC[e4 * 4 + 3] += kc * v4.w;
            aS[e4 * 4 + 0] += ks * v4.x; aS[e4 * 4 + 1] += ks * v4.y;
            aS[e4 * 4 + 2] += ks * v4.z; aS[e4 * 4 + 3] += ks * v4.w;
        }
    }

    size_t base = (size_t)(h * NCH + c) * 2 * DDIM * DDIM;
    #pragma unroll
    for (int e = 0; e < 16; e++) {
        g_ckv[base + d * DDIM + eg + e]               = aC[e];
        g_ckv[base + DDIM * DDIM + d * DDIM + eg + e] = aS[e];
    }

    if (tid < DDIM) {
        float sc = 0.f, ss = 0.f;
        for (int i = 0; i < CHUNK; i++) {
            float kd = rk[i * DDIM + tid];
            sc += kd * cw[i];
            ss += kd * sw[i];
        }
        size_t kb = (size_t)(h * NCH + c) * 2 * DDIM;
        g_ck[kb + tid]        = sc;
        g_ck[kb + DDIM + tid] = ss;
    }
}

// ---------------------------------------------------------------------------
// scan: exclusive prefix over 32 chunks. grid 256 x 256, one thread per lane.
// ---------------------------------------------------------------------------
__global__ __launch_bounds__(256)
void scan_kernel() {
    const int h = blockIdx.x >> 5;
    const int idx = (blockIdx.x & 31) * 256 + threadIdx.x;  // 0..8191
    const int KVSZ = 2 * DDIM * DDIM;  // 8192

    float v[NCH];
    #pragma unroll
    for (int c = 0; c < NCH; c++)
        v[c] = g_ckv[(size_t)(h * NCH + c) * KVSZ + idx];
    float run = 0.f;
    #pragma unroll
    for (int c = 0; c < NCH; c++) {
        g_pkv[(size_t)(h * NCH + c) * KVSZ + idx] = run;
        run += v[c];
    }

    if ((blockIdx.x & 31) == 0 && threadIdx.x < 2 * DDIM) {
        const int t = threadIdx.x;
        const int KSZ = 2 * DDIM;
        float w[NCH];
        #pragma unroll
        for (int c = 0; c < NCH; c++)
            w[c] = g_ck[(size_t)(h * NCH + c) * KSZ + t];
        float r2 = 0.f;
        #pragma unroll
        for (int c = 0; c < NCH; c++) {
            g_pk[(size_t)(h * NCH + c) * KSZ + t] = r2;
            r2 += w[c];
        }
    }
}

// ---------------------------------------------------------------------------
// chunk_out (C=64): register-tiled, predicated-causal, fp16 in/out.
// grid (NCH, HEADS) = 256 blocks, 256 threads. Parallel nrm (4 thr/row).
// ---------------------------------------------------------------------------
#define RQT_STRIDE 68
#define S_STRIDE   66

__global__ __launch_bounds__(256)
void chunk_out_kernel() {
    extern __shared__ float smf[];
    float* rqT = smf;                       // [64][68]
    float* rkT = rqT + DDIM * RQT_STRIDE;   // [64][68]
    float* vv  = rkT + DDIM * RQT_STRIDE;   // [64][64]
    float* S   = vv + CHUNK * DDIM;         // [64][66]
    float* KVc = S + CHUNK * S_STRIDE;      // [64][64]
    float* KVs = KVc + DDIM * DDIM;         // [64][64]
    float* K0c = KVs + DDIM * DDIM;         // [64]
    float* K0s = K0c + DDIM;                // [64]
    float* cw  = K0s + DDIM;                // [64]
    float* sw  = cw + CHUNK;                // [64]
    float* nrm = sw + CHUNK;                // [64]
    float* nrm4 = nrm + CHUNK;              // [4][64]

    const int c = blockIdx.x, h = blockIdx.y, tid = threadIdx.x;

    for (int t = tid; t < CHUNK * DDIM / 2; t += 256) {
        int i = t >> 5, d2 = t & 31;        // d = d2*2
        const __half* row = g_qkvh + (size_t)(c * CHUNK + i) * E3 + h * DDIM;
        float2 qf = __half22float2(*reinterpret_cast<const __half2*>(&row[d2 * 2]));
        float2 kf = __half22float2(*reinterpret_cast<const __half2*>(&row[EDIM + d2 * 2]));
        float2 vf = __half22float2(*reinterpret_cast<const __half2*>(&row[2 * EDIM + d2 * 2]));
        rqT[(d2 * 2) * RQT_STRIDE + i]     = qf.x;
        rqT[(d2 * 2 + 1) * RQT_STRIDE + i] = qf.y;
        rkT[(d2 * 2) * RQT_STRIDE + i]     = kf.x;
        rkT[(d2 * 2 + 1) * RQT_STRIDE + i] = kf.y;
        vv[i * DDIM + d2 * 2]              = vf.x;
        vv[i * DDIM + d2 * 2 + 1]          = vf.y;
    }
    if (tid < CHUNK) {
        float th = (float)(c * CHUNK + tid) * THETA_SCALE;
        cw[tid] = cosf(th);
        sw[tid] = sinf(th);
    }
    {
        const float* base = g_pkv + (size_t)(h * NCH + c) * 2 * DDIM * DDIM;
        for (int t = tid; t < 2 * DDIM * DDIM; t += 256) {
            if (t < DDIM * DDIM) KVc[t] = base[t];
            else                 KVs[t - DDIM * DDIM] = base[t];
        }
        const float* kb = g_pk + (size_t)(h * NCH + c) * 2 * DDIM;
        if (tid < 2 * DDIM) {
            if (tid < DDIM) K0c[tid] = kb[tid];
            else            K0s[tid - DDIM] = kb[tid];
        }
    }
    __syncthreads();

    // ---- phase 1: S[i][j] (j<=i), 4x4 tiles on a 16x16 thread grid
    {
        const int ti = tid >> 4, tj = tid & 15;
        const int i0 = ti * 4, j0 = tj * 4;
        if (j0 <= i0 + 3) {
            float acc[4][4];
            #pragma unroll
            for (int r = 0; r < 4; r++)
                #pragma unroll
                for (int q = 0; q < 4; q++) acc[r][q] = 0.f;

            for (int d = 0; d < DDIM; d++) {
                float4 a4 = *reinterpret_cast<const float4*>(&rqT[d * RQT_STRIDE + i0]);
                float4 b4 = *reinterpret_cast<const float4*>(&rkT[d * RQT_STRIDE + j0]);
                float a[4] = {a4.x, a4.y, a4.z, a4.w};
                float b[4] = {b4.x, b4.y, b4.z, b4.w};
                #pragma unroll
                for (int r = 0; r < 4; r++)
                    #pragma unroll
                    for (int q = 0; q < 4; q++)
                        acc[r][q] += a[r] * b[q];
            }
            #pragma unroll
            for (int r = 0; r < 4; r++) {
                int i = i0 + r;
                float ci = cw[i], si = sw[i];
                #pragma unroll
                for (int q = 0; q < 4; q++) {
                    int j = j0 + q;
                    if (j <= i)
                        S[i * S_STRIDE + j] = acc[r][q] * (ci * cw[j] + si * sw[j]);
                }
            }
        }
    }
    __syncthreads();

    // ---- phase 2: nrm, 4 threads per row
    {
        const int i2 = tid & 63, qd = tid >> 6;
        float dc = 0.f, ds = 0.f;
        #pragma unroll
        for (int dd = 0; dd < 16; dd++) {
            int d = qd * 16 + dd;
            float q = rqT[d * RQT_STRIDE + i2];
            dc += q * K0c[d];
            ds += q * K0s[d];
        }
        float part = cw[i2] * dc + sw[i2] * ds;
        int jbeg = qd * 16;
        int jend = (i2 < jbeg + 15) ? i2 : (jbeg + 15);
        for (int j = jbeg; j <= jend; j++) part += S[i2 * S_STRIDE + j];
        nrm4[qd * 64 + i2] = part;
    }
    __syncthreads();
    if (tid < CHUNK)
        nrm[tid] = nrm4[tid] + nrm4[64 + tid] + nrm4[128 + tid] + nrm4[192 + tid];
    __syncthreads();

    // ---- phase 3: 2 rows x 8 cols per thread
    const int tx = tid & 7, ty = tid >> 3;
    const int e0 = tx * 8, i0 = ty * 2;

    float tC[2][8], tS[2][8], tI[2][8];
    #pragma unroll
    for (int r = 0; r < 2; r++)
        #pragma unroll
        for (int e = 0; e < 8; e++) { tC[r][e] = 0.f; tS[r][e] = 0.f; tI[r][e] = 0.f; }

    for (int d = 0; d < DDIM; d++) {
        float2 q2 = *reinterpret_cast<const float2*>(&rqT[d * RQT_STRIDE + i0]);
        float qr[2] = {q2.x, q2.y};
        float4 c0 = *reinterpret_cast<const float4*>(&KVc[d * DDIM + e0]);
        float4 c1 = *reinterpret_cast<const float4*>(&KVc[d * DDIM + e0 + 4]);
        float4 s0 = *reinterpret_cast<const float4*>(&KVs[d * DDIM + e0]);
        float4 s1 = *reinterpret_cast<const float4*>(&KVs[d * DDIM + e0 + 4]);
        float cv[8] = {c0.x, c0.y, c0.z, c0.w, c1.x, c1.y, c1.z, c1.w};
        float sv[8] = {s0.x, s0.y, s0.z, s0.w, s1.x, s1.y, s1.z, s1.w};
        #pragma unroll
        for (int r = 0; r < 2; r++)
            #pragma unroll
            for (int e = 0; e < 8; e++) {
                tC[r][e] += qr[r] * cv[e];
                tS[r][e] += qr[r] * sv[e];
            }
    }

    for (int j = 0; j <= i0; j++) {
        float sr[2];
        #pragma unroll
        for (int r = 0; r < 2; r++) sr[r] = S[(i0 + r) * S_STRIDE + j];
        float4 v0 = *reinterpret_cast<const float4*>(&vv[j * DDIM + e0]);
        float4 v1 = *reinterpret_cast<const float4*>(&vv[j * DDIM + e0 + 4]);
        float ve[8] = {v0.x, v0.y, v0.z, v0.w, v1.x, v1.y, v1.z, v1.w};
        #pragma unroll
        for (int r = 0; r < 2; r++)
            #pragma unroll
            for (int e = 0; e < 8; e++)
                tI[r][e] += sr[r] * ve[e];
    }
    {   // tail j = i0+1, valid only for r=1
        const int j = i0 + 1;
        float s1 = S[(i0 + 1) * S_STRIDE + j];
        float4 v0 = *reinterpret_cast<const float4*>(&vv[j * DDIM + e0]);
        float4 v1 = *reinterpret_cast<const float4*>(&vv[j * DDIM + e0 + 4]);
        float ve[8] = {v0.x, v0.y, v0.z, v0.w, v1.x, v1.y, v1.z, v1.w};
        #pragma unroll
        for (int e = 0; e < 8; e++)
            tI[1][e] += s1 * ve[e];
    }

    // ---- epilogue: combine, normalize, fp16 round, store
    #pragma unroll
    for (int r = 0; r < 2; r++) {
        const int i = i0 + r;
        float ci = cw[i], si = sw[i];
        float inv = 1.0f / (nrm[i] + 1e-6f);
        uint32_t ph[4];
        #pragma unroll
        for (int e2 = 0; e2 < 4; e2++) {
            float v0 = (ci * tC[r][e2 * 2 + 0] + si * tS[r][e2 * 2 + 0] + tI[r][e2 * 2 + 0]) * inv;
            float v1 = (ci * tC[r][e2 * 2 + 1] + si * tS[r][e2 * 2 + 1] + tI[r][e2 * 2 + 1]) * inv;
            __half h0 = __float2half(v0);
            __half h1 = __float2half(v1);
            ph[e2] = (uint32_t)__half_as_ushort(h0) |
                     ((uint32_t)__half_as_ushort(h1) << 16);
        }
        size_t base = (size_t)(c * CHUNK + i) * EDIM + h * DDIM + e0;
        *reinterpret_cast<uint4*>(&g_ah[base]) = make_uint4(ph[0], ph[1], ph[2], ph[3]);
    }
}

// ---------------------------------------------------------------------------

static const int SMEM_SUM = (2 * CHUNK * DDIM + 2 * CHUNK) * (int)sizeof(float);
static const int SMEM_OUT = (2 * DDIM * RQT_STRIDE + CHUNK * DDIM + CHUNK * S_STRIDE +
                             2 * DDIM * DDIM + 2 * DDIM + 3 * CHUNK + 4 * CHUNK) * (int)sizeof(float);

extern "C" void kernel_launch(void* const* d_in, const int* in_sizes, int n_in,
                              void* d_out, int out_size) {
    (void)in_sizes; (void)n_in; (void)out_size;
    const float* x    = (const float*)d_in[0];
    const float* Wqkv = (const float*)d_in[1];
    const float* bqkv = (const float*)d_in[2];
    const float* Wout = (const float*)d_in[3];
    const float* bout = (const float*)d_in[4];
    float* out = (float*)d_out;

    __half *qkvh, *xh, *wqh, *woh, *ah;
    cudaGetSymbolAddress((void**)&qkvh, g_qkvh);
    cudaGetSymbolAddress((void**)&xh, g_xh);
    cudaGetSymbolAddress((void**)&wqh, g_wqh);
    cudaGetSymbolAddress((void**)&woh, g_woh);
    cudaGetSymbolAddress((void**)&ah, g_ah);

    cudaFuncSetAttribute(chunk_sum_kernel,
                         cudaFuncAttributeMaxDynamicSharedMemorySize, SMEM_SUM);
    cudaFuncSetAttribute(chunk_out_kernel,
                         cudaFuncAttributeMaxDynamicSharedMemorySize, SMEM_OUT);
    cudaFuncSetAttribute((const void*)mma_gemm_kernel<64, true>,
                         cudaFuncAttributeMaxDynamicSharedMemorySize, GSMEM(64));
    cudaFuncSetAttribute((const void*)mma_gemm_kernel<32, false>,
                         cudaFuncAttributeMaxDynamicSharedMemorySize, GSMEM(32));

    // fp16 conversions: x + Wqkv^T + Wout^T, one launch
    split_all_kernel<<<1024 + 768 + 256, 256>>>(x, Wqkv, Wout);

    // 1) QKV GEMM -> fp16 QKV with fused relu on Q,K cols
    mma_gemm_kernel<64, true><<<dim3(E3 / 128, LSEQ / 64), 256, GSMEM(64)>>>(
        xh, wqh, bqkv, qkvh, E3, EDIM);

    // 2) Chunked cosformer attention
    chunk_sum_kernel<<<dim3(NCH, HEADS), 256, SMEM_SUM>>>();
    scan_kernel<<<256, 256>>>();
    chunk_out_kernel<<<dim3(NCH, HEADS), 256, SMEM_OUT>>>();

    // 3) Output GEMM: fp32 out
    mma_gemm_kernel<32, false><<<dim3(EDIM / 128, LSEQ / 32), 256, GSMEM(32)>>>(
        ah, woh, bout, out, EDIM, EDIM);
}

// round 17
// speedup vs baseline: 1.2357x; 1.0235x over previous
#include <cuda_runtime.h>
#include <cuda_fp16.h>
#include <cstdint>
#include <cstddef>

// Problem constants
#define LSEQ 2048
#define EDIM 512
#define HEADS 8
#define DDIM 64
#define E3   1536
#define CHUNK 64
#define NCH  32

#define THETA_SCALE 7.66990393942820573e-4f  // (pi/2)/2048

// ---------------- scratch (device globals; no allocs allowed) ----------------
__device__ __half g_qkvh[LSEQ * E3];   // fp16 QKV, relu pre-applied to Q,K cols
__device__ __half g_ckv[HEADS * NCH * 2 * DDIM * DDIM];  // fp16 chunk KV sums
__device__ float  g_ck [HEADS * NCH * 2 * DDIM];
__device__ __half g_pkv[HEADS * NCH * 2 * DDIM * DDIM];  // fp16 prefix KV
__device__ float  g_pk [HEADS * NCH * 2 * DDIM];

// fp16 buffers
__device__ __half g_xh[LSEQ * EDIM];
__device__ __half g_wqh[E3 * EDIM];   // Wqkv^T  [1536][512]
__device__ __half g_woh[EDIM * EDIM]; // Wout^T  [512][512]
__device__ __half g_ah[LSEQ * EDIM];  // attention out (fp16)

// ---------------- low-level helpers ----------------
__device__ __forceinline__ uint32_t smem_u32(const void* p) {
    uint32_t a;
    asm("{ .reg .u64 t; cvta.to.shared.u64 t, %1; cvt.u32.u64 %0, t; }"
        : "=r"(a) : "l"(p));
    return a;
}
#define CP_ASYNC16(dst, src) \
    asm volatile("cp.async.cg.shared.global [%0], [%1], 16;" :: "r"(dst), "l"(src))
#define CP_COMMIT() asm volatile("cp.async.commit_group;" ::: "memory")
#define CP_WAIT0()  asm volatile("cp.async.wait_group 0;" ::: "memory")
#define CP_WAIT1()  asm volatile("cp.async.wait_group 1;" ::: "memory")
#define CP_WAIT2()  asm volatile("cp.async.wait_group 2;" ::: "memory")

__device__ __forceinline__ void ldmx4(uint32_t* r, uint32_t addr) {
    asm volatile("ldmatrix.sync.aligned.m8n8.x4.shared.b16 {%0,%1,%2,%3}, [%4];"
                 : "=r"(r[0]), "=r"(r[1]), "=r"(r[2]), "=r"(r[3]) : "r"(addr));
}
__device__ __forceinline__ void mma16816(float* c, const uint32_t* a, const uint32_t* b) {
    asm volatile(
        "mma.sync.aligned.m16n8k16.row.col.f32.f16.f16.f32 "
        "{%0,%1,%2,%3}, {%4,%5,%6,%7}, {%8,%9}, {%0,%1,%2,%3};"
        : "+f"(c[0]), "+f"(c[1]), "+f"(c[2]), "+f"(c[3])
        : "r"(a[0]), "r"(a[1]), "r"(a[2]), "r"(a[3]), "r"(b[0]), "r"(b[1]));
}

// ---------------- fused split kernel: x fp16 + both weight transposes ------
__device__ __forceinline__ void transpose_half_tile(
    const float* __restrict__ W, __half* __restrict__ hiT,
    int K, int N, int bx, int by, float (*t)[33]) {
    const int tx = threadIdx.x & 31, ty = threadIdx.x >> 5;  // (32, 8)
    const int n0 = bx * 32, k0 = by * 32;
    #pragma unroll
    for (int j = 0; j < 4; j++)
        t[ty + 8 * j][tx] = W[(size_t)(k0 + ty + 8 * j) * N + n0 + tx];
    __syncthreads();
    #pragma unroll
    for (int j = 0; j < 4; j++)
        hiT[(size_t)(n0 + ty + 8 * j) * K + k0 + tx] = __float2half(t[tx][ty + 8 * j]);
}

__global__ __launch_bounds__(256)
void split_all_kernel(const float* __restrict__ x,
                      const float* __restrict__ Wqkv,
                      const float* __restrict__ Wout) {
    __shared__ float t[32][33];
    const int b = blockIdx.x;
    if (b < 1024) {
        int i = b * 1024 + threadIdx.x * 4;
        float4 a4 = *reinterpret_cast<const float4*>(&x[i]);
        __half hv[4] = {__float2half(a4.x), __float2half(a4.y),
                        __float2half(a4.z), __float2half(a4.w)};
        *reinterpret_cast<uint2*>(&g_xh[i]) = *reinterpret_cast<uint2*>(hv);
    } else if (b < 1024 + 768) {
        int tt = b - 1024;                 // Wqkv: K=512, N=1536 -> 48 x 16 tiles
        transpose_half_tile(Wqkv, g_wqh, EDIM, E3, tt % 48, tt / 48, t);
    } else {
        int tt = b - 1024 - 768;           // Wout: K=512, N=512 -> 16 x 16 tiles
        transpose_half_tile(Wout, g_woh, EDIM, EDIM, tt % 16, tt / 16, t);
    }
}

// ---------------- mma.sync fp16 GEMM: C[M,N] = A @ Bt^T + bias --------------
#define KC 32
#define AST 40   // smem row stride in fp16 elems

template<int BM, bool HOUT>
__global__ __launch_bounds__(256, 4)
void mma_gemm_kernel(const __half* __restrict__ Ah,
                     const __half* __restrict__ Bh,
                     const float* __restrict__ bias, void* __restrict__ Cv,
                     int N, int K) {
    constexpr int MI = BM / 32;
    constexpr int TILE_A = BM * AST;
    constexpr int TILE_B = 128 * AST;
    constexpr int BUF_E  = TILE_A + TILE_B;

    extern __shared__ __half smem[];
    const int tid = threadIdx.x;
    const int wid = tid >> 5, lane = tid & 31;
    const int bn0 = blockIdx.x * 128, bm0 = blockIdx.y * BM;
    const int wm = (wid & 1) * (BM / 2);
    const int wn = (wid >> 1) * 32;

    const uint32_t smb = smem_u32(smem);
    const int NCHK = K / KC;

    float acc[MI][4][4];
    #pragma unroll
    for (int mi = 0; mi < MI; mi++)
        #pragma unroll
        for (int nj = 0; nj < 4; nj++)
            #pragma unroll
            for (int r = 0; r < 4; r++) acc[mi][nj][r] = 0.f;

    const __half* srcs[2] = {Ah, Bh};
    const int  srow[2] = {bm0, bn0};
    const int  titem[2] = {BM * KC / 8, 128 * KC / 8};
    const uint32_t toff[2] = {0u, (uint32_t)TILE_A};

    auto load_chunk = [&](int b, int k0) {
        #pragma unroll
        for (int t = 0; t < 2; t++) {
            const __half* s = srcs[t];
            uint32_t dbase = smb + (uint32_t)(b * BUF_E + toff[t]) * 2u;
            const int nit = titem[t];
            for (int item = tid; item < nit; item += 256) {
                int row = item >> 2, sub = item & 3;
                uint32_t d = dbase + (uint32_t)(row * AST + sub * 8) * 2u;
                const void* g = (const void*)(s + (size_t)(srow[t] + row) * K + k0 + sub * 8);
                CP_ASYNC16(d, g);
            }
        }
        CP_COMMIT();
    };

    load_chunk(0, 0);
    load_chunk(1, KC);

    for (int c = 0; c < NCHK; c++) {
        const int b = c % 3;
        if (c + 2 < NCHK) load_chunk((c + 2) % 3, (c + 2) * KC);
        if (c + 2 < NCHK)      CP_WAIT2();
        else if (c + 1 < NCHK) CP_WAIT1();
        else                   CP_WAIT0();
        __syncthreads();

        const uint32_t aB = smb + (uint32_t)(b * BUF_E) * 2u;
        const uint32_t bB = aB + (uint32_t)TILE_A * 2u;

        #pragma unroll
        for (int ks = 0; ks < KC; ks += 16) {
            const int arow = wm + (lane & 15);
            const int acol = ks + ((lane >> 4) << 3);
            uint32_t ah[MI][4];
            #pragma unroll
            for (int mi = 0; mi < MI; mi++) {
                uint32_t off = (uint32_t)((arow + mi * 16) * AST + acol) * 2u;
                ldmx4(ah[mi], aB + off);
            }
            const int brow = wn + (lane & 7) + ((lane & 16) ? 8 : 0);
            const int bcol = ks + ((lane & 8) ? 8 : 0);
            uint32_t bh[2][4];
            #pragma unroll
            for (int ni = 0; ni < 2; ni++) {
                uint32_t off = (uint32_t)((brow + ni * 16) * AST + bcol) * 2u;
                ldmx4(bh[ni], bB + off);
            }
            #pragma unroll
            for (int mi = 0; mi < MI; mi++) {
                #pragma unroll
                for (int nj = 0; nj < 4; nj++) {
                    const uint32_t* ph = &bh[nj >> 1][(nj & 1) * 2];
                    mma16816(acc[mi][nj], ah[mi], ph);
                }
            }
        }
        __syncthreads();
    }

    const int r0 = bm0 + wm + (lane >> 2);
    const int c0 = bn0 + wn + (lane & 3) * 2;
    #pragma unroll
    for (int mi = 0; mi < MI; mi++) {
        #pragma unroll
        for (int nj = 0; nj < 4; nj++) {
            int row = r0 + mi * 16;
            int col = c0 + nj * 8;
            float b0 = bias[col], b1 = bias[col + 1];
            float v00 = acc[mi][nj][0] + b0, v01 = acc[mi][nj][1] + b1;
            float v10 = acc[mi][nj][2] + b0, v11 = acc[mi][nj][3] + b1;
            if constexpr (HOUT) {
                __half* Ch = (__half*)Cv;
                if (col < 2 * EDIM) {  // Q,K region: fuse relu
                    v00 = fmaxf(v00, 0.f); v01 = fmaxf(v01, 0.f);
                    v10 = fmaxf(v10, 0.f); v11 = fmaxf(v11, 0.f);
                }
                *reinterpret_cast<__half2*>(&Ch[(size_t)row * N + col]) =
                    __floats2half2_rn(v00, v01);
                *reinterpret_cast<__half2*>(&Ch[(size_t)(row + 8) * N + col]) =
                    __floats2half2_rn(v10, v11);
            } else {
                float* Cf = (float*)Cv;
                *reinterpret_cast<float2*>(&Cf[(size_t)row * N + col]) = make_float2(v00, v01);
                *reinterpret_cast<float2*>(&Cf[(size_t)(row + 8) * N + col]) = make_float2(v10, v11);
            }
        }
    }
}

// smem bytes: 3 buffers x (BM + 128) * AST * 2 bytes
#define GSMEM(BM) ((BM + 128) * AST * 6)

// ---------------------------------------------------------------------------
// chunk_sum: per-chunk (C=64) KV / K sums -> fp16. grid (NCH, HEADS).
// ---------------------------------------------------------------------------
__global__ __launch_bounds__(256)
void chunk_sum_kernel() {
    extern __shared__ float smf[];
    float* rk = smf;                 // [64][64]
    float* vv = rk + CHUNK * DDIM;   // [64][64]
    float* cw = vv + CHUNK * DDIM;   // [64]
    float* sw = cw + CHUNK;          // [64]

    const int c = blockIdx.x, h = blockIdx.y, tid = threadIdx.x;

    for (int t = tid; t < CHUNK * DDIM / 2; t += 256) {
        int i = t >> 5, d2 = t & 31;
        const __half* row = g_qkvh + (size_t)(c * CHUNK + i) * E3 + h * DDIM;
        float2 kf = __half22float2(*reinterpret_cast<const __half2*>(&row[EDIM + d2 * 2]));
        float2 vf = __half22float2(*reinterpret_cast<const __half2*>(&row[2 * EDIM + d2 * 2]));
        rk[i * DDIM + d2 * 2]     = kf.x;
        rk[i * DDIM + d2 * 2 + 1] = kf.y;
        vv[i * DDIM + d2 * 2]     = vf.x;
        vv[i * DDIM + d2 * 2 + 1] = vf.y;
    }
    if (tid < CHUNK) {
        float th = (float)(c * CHUNK + tid) * THETA_SCALE;
        cw[tid] = cosf(th);
        sw[tid] = sinf(th);
    }
    __syncthreads();

    const int d  = tid & 63;
    const int eg = (tid >> 6) << 4;
    float aC[16], aS[16];
    #pragma unroll
    for (int e = 0; e < 16; e++) { aC[e] = 0.f; aS[e] = 0.f; }

    for (int i = 0; i < CHUNK; i++) {
        float kd = rk[i * DDIM + d];
        float kc = kd * cw[i];
        float ks = kd * sw[i];
        const float4* vp = reinterpret_cast<const float4*>(&vv[i * DDIM + eg]);
        #pragma unroll
        for (int e4 = 0; e4 < 4; e4++) {
            float4 v4 = vp[e4];
            aC[e4 * 4 + 0] += kc * v4.x; aC[e4 * 4 + 1] += kc * v4.y;
            aC[e4 * 4 + 2] += kc * v4.z; aC[e4 * 4 + 3] += kc * v4.w;
            aS[e4 * 4 + 0] += ks * v4.x; aS[e4 * 4 + 1] += ks * v4.y;
            aS[e4 * 4 + 2] += ks * v4.z; aS[e4 * 4 + 3] += ks * v4.w;
        }
    }

    size_t base = (size_t)(h * NCH + c) * 2 * DDIM * DDIM;
    __half2* pc = reinterpret_cast<__half2*>(&g_ckv[base + d * DDIM + eg]);
    __half2* ps = reinterpret_cast<__half2*>(&g_ckv[base + DDIM * DDIM + d * DDIM + eg]);
    #pragma unroll
    for (int e2 = 0; e2 < 8; e2++) {
        pc[e2] = __floats2half2_rn(aC[e2 * 2], aC[e2 * 2 + 1]);
        ps[e2] = __floats2half2_rn(aS[e2 * 2], aS[e2 * 2 + 1]);
    }

    if (tid < DDIM) {
        float sc = 0.f, ss = 0.f;
        for (int i = 0; i < CHUNK; i++) {
            float kd = rk[i * DDIM + tid];
            sc += kd * cw[i];
            ss += kd * sw[i];
        }
        size_t kb = (size_t)(h * NCH + c) * 2 * DDIM;
        g_ck[kb + tid]        = sc;
        g_ck[kb + DDIM + tid] = ss;
    }
}

// ---------------------------------------------------------------------------
// scan: exclusive prefix over 32 chunks (fp16 io, fp32 accum).
// grid 128 x 256, one thread per half2 lane (2 values).
// ---------------------------------------------------------------------------
__global__ __launch_bounds__(256)
void scan_kernel() {
    const int h = blockIdx.x >> 4;                       // 8 heads x 16 blocks
    const int q = (blockIdx.x & 15) * 256 + threadIdx.x; // half2 lane 0..4095
    const int KV2 = 2 * DDIM * DDIM / 2;                 // 4096

    const __half2* src = reinterpret_cast<const __half2*>(g_ckv);
    __half2* dst = reinterpret_cast<__half2*>(g_pkv);

    __half2 v[NCH];
    #pragma unroll
    for (int c = 0; c < NCH; c++)
        v[c] = src[(size_t)(h * NCH + c) * KV2 + q];
    float rx = 0.f, ry = 0.f;
    #pragma unroll
    for (int c = 0; c < NCH; c++) {
        dst[(size_t)(h * NCH + c) * KV2 + q] = __floats2half2_rn(rx, ry);
        float2 f = __half22float2(v[c]);
        rx += f.x; ry += f.y;
    }

    if ((blockIdx.x & 15) == 0 && threadIdx.x < 2 * DDIM) {
        const int t = threadIdx.x;
        const int KSZ = 2 * DDIM;
        float w[NCH];
        #pragma unroll
        for (int c = 0; c < NCH; c++)
            w[c] = g_ck[(size_t)(h * NCH + c) * KSZ + t];
        float r2 = 0.f;
        #pragma unroll
        for (int c = 0; c < NCH; c++) {
            g_pk[(size_t)(h * NCH + c) * KSZ + t] = r2;
            r2 += w[c];
        }
    }
}

// ---------------------------------------------------------------------------
// chunk_out (C=64): register-tiled, predicated-causal, fp16 in/out.
// grid (NCH, HEADS) = 256 blocks, 256 threads. Parallel nrm (4 thr/row).
// ---------------------------------------------------------------------------
#define RQT_STRIDE 68
#define S_STRIDE   66

__global__ __launch_bounds__(256)
void chunk_out_kernel() {
    extern __shared__ float smf[];
    float* rqT = smf;                       // [64][68]
    float* rkT = rqT + DDIM * RQT_STRIDE;   // [64][68]
    float* vv  = rkT + DDIM * RQT_STRIDE;   // [64][64]
    float* S   = vv + CHUNK * DDIM;         // [64][66]
    float* KVc = S + CHUNK * S_STRIDE;      // [64][64]
    float* KVs = KVc + DDIM * DDIM;         // [64][64]
    float* K0c = KVs + DDIM * DDIM;         // [64]
    float* K0s = K0c + DDIM;                // [64]
    float* cw  = K0s + DDIM;                // [64]
    float* sw  = cw + CHUNK;                // [64]
    float* nrm = sw + CHUNK;                // [64]
    float* nrm4 = nrm + CHUNK;              // [4][64]

    const int c = blockIdx.x, h = blockIdx.y, tid = threadIdx.x;

    for (int t = tid; t < CHUNK * DDIM / 2; t += 256) {
        int i = t >> 5, d2 = t & 31;
        const __half* row = g_qkvh + (size_t)(c * CHUNK + i) * E3 + h * DDIM;
        float2 qf = __half22float2(*reinterpret_cast<const __half2*>(&row[d2 * 2]));
        float2 kf = __half22float2(*reinterpret_cast<const __half2*>(&row[EDIM + d2 * 2]));
        float2 vf = __half22float2(*reinterpret_cast<const __half2*>(&row[2 * EDIM + d2 * 2]));
        rqT[(d2 * 2) * RQT_STRIDE + i]     = qf.x;
        rqT[(d2 * 2 + 1) * RQT_STRIDE + i] = qf.y;
        rkT[(d2 * 2) * RQT_STRIDE + i]     = kf.x;
        rkT[(d2 * 2 + 1) * RQT_STRIDE + i] = kf.y;
        vv[i * DDIM + d2 * 2]              = vf.x;
        vv[i * DDIM + d2 * 2 + 1]          = vf.y;
    }
    if (tid < CHUNK) {
        float th = (float)(c * CHUNK + tid) * THETA_SCALE;
        cw[tid] = cosf(th);
        sw[tid] = sinf(th);
    }
    {
        const __half2* base2 = reinterpret_cast<const __half2*>(
            g_pkv + (size_t)(h * NCH + c) * 2 * DDIM * DDIM);
        for (int t = tid; t < DDIM * DDIM; t += 256) {   // 4096 half2
            float2 f = __half22float2(base2[t]);
            if (t < DDIM * DDIM / 2) {
                KVc[t * 2]     = f.x;
                KVc[t * 2 + 1] = f.y;
            } else {
                int u = t - DDIM * DDIM / 2;
                KVs[u * 2]     = f.x;
                KVs[u * 2 + 1] = f.y;
            }
        }
        const float* kb = g_pk + (size_t)(h * NCH + c) * 2 * DDIM;
        if (tid < 2 * DDIM) {
            if (tid < DDIM) K0c[tid] = kb[tid];
            else            K0s[tid - DDIM] = kb[tid];
        }
    }
    __syncthreads();

    // ---- phase 1: S[i][j] (j<=i), 4x4 tiles on a 16x16 thread grid
    {
        const int ti = tid >> 4, tj = tid & 15;
        const int i0 = ti * 4, j0 = tj * 4;
        if (j0 <= i0 + 3) {
            float acc[4][4];
            #pragma unroll
            for (int r = 0; r < 4; r++)
                #pragma unroll
                for (int q = 0; q < 4; q++) acc[r][q] = 0.f;

            for (int d = 0; d < DDIM; d++) {
                float4 a4 = *reinterpret_cast<const float4*>(&rqT[d * RQT_STRIDE + i0]);
                float4 b4 = *reinterpret_cast<const float4*>(&rkT[d * RQT_STRIDE + j0]);
                float a[4] = {a4.x, a4.y, a4.z, a4.w};
                float b[4] = {b4.x, b4.y, b4.z, b4.w};
                #pragma unroll
                for (int r = 0; r < 4; r++)
                    #pragma unroll
                    for (int q = 0; q < 4; q++)
                        acc[r][q] += a[r] * b[q];
            }
            #pragma unroll
            for (int r = 0; r < 4; r++) {
                int i = i0 + r;
                float ci = cw[i], si = sw[i];
                #pragma unroll
                for (int q = 0; q < 4; q++) {
                    int j = j0 + q;
                    if (j <= i)
                        S[i * S_STRIDE + j] = acc[r][q] * (ci * cw[j] + si * sw[j]);
                }
            }
        }
    }
    __syncthreads();

    // ---- phase 2: nrm, 4 threads per row
    {
        const int i2 = tid & 63, qd = tid >> 6;
        float dc = 0.f, ds = 0.f;
        #pragma unroll
        for (int dd = 0; dd < 16; dd++) {
            int d = qd * 16 + dd;
            float q = rqT[d * RQT_STRIDE + i2];
            dc += q * K0c[d];
            ds += q * K0s[d];
        }
        float part = cw[i2] * dc + sw[i2] * ds;
        int jbeg = qd * 16;
        int jend = (i2 < jbeg + 15) ? i2 : (jbeg + 15);
        for (int j = jbeg; j <= jend; j++) part += S[i2 * S_STRIDE + j];
        nrm4[qd * 64 + i2] = part;
    }
    __syncthreads();
    if (tid < CHUNK)
        nrm[tid] = nrm4[tid] + nrm4[64 + tid] + nrm4[128 + tid] + nrm4[192 + tid];
    __syncthreads();

    // ---- phase 3: 2 rows x 8 cols per thread
    const int tx = tid & 7, ty = tid >> 3;
    const int e0 = tx * 8, i0 = ty * 2;

    float tC[2][8], tS[2][8], tI[2][8];
    #pragma unroll
    for (int r = 0; r < 2; r++)
        #pragma unroll
        for (int e = 0; e < 8; e++) { tC[r][e] = 0.f; tS[r][e] = 0.f; tI[r][e] = 0.f; }

    for (int d = 0; d < DDIM; d++) {
        float2 q2 = *reinterpret_cast<const float2*>(&rqT[d * RQT_STRIDE + i0]);
        float qr[2] = {q2.x, q2.y};
        float4 c0 = *reinterpret_cast<const float4*>(&KVc[d * DDIM + e0]);
        float4 c1 = *reinterpret_cast<const float4*>(&KVc[d * DDIM + e0 + 4]);
        float4 s0 = *reinterpret_cast<const float4*>(&KVs[d * DDIM + e0]);
        float4 s1 = *reinterpret_cast<const float4*>(&KVs[d * DDIM + e0 + 4]);
        float cv[8] = {c0.x, c0.y, c0.z, c0.w, c1.x, c1.y, c1.z, c1.w};
        float sv[8] = {s0.x, s0.y, s0.z, s0.w, s1.x, s1.y, s1.z, s1.w};
        #pragma unroll
        for (int r = 0; r < 2; r++)
            #pragma unroll
            for (int e = 0; e < 8; e++) {
                tC[r][e] += qr[r] * cv[e];
                tS[r][e] += qr[r] * sv[e];
            }
    }

    for (int j = 0; j <= i0; j++) {
        float sr[2];
        #pragma unroll
        for (int r = 0; r < 2; r++) sr[r] = S[(i0 + r) * S_STRIDE + j];
        float4 v0 = *reinterpret_cast<const float4*>(&vv[j * DDIM + e0]);
        float4 v1 = *reinterpret_cast<const float4*>(&vv[j * DDIM + e0 + 4]);
        float ve[8] = {v0.x, v0.y, v0.z, v0.w, v1.x, v1.y, v1.z, v1.w};
        #pragma unroll
        for (int r = 0; r < 2; r++)
            #pragma unroll
            for (int e = 0; e < 8; e++)
                tI[r][e] += sr[r] * ve[e];
    }
    {   // tail j = i0+1, valid only for r=1
        const int j = i0 + 1;
        float s1 = S[(i0 + 1) * S_STRIDE + j];
        float4 v0 = *reinterpret_cast<const float4*>(&vv[j * DDIM + e0]);
        float4 v1 = *reinterpret_cast<const float4*>(&vv[j * DDIM + e0 + 4]);
        float ve[8] = {v0.x, v0.y, v0.z, v0.w, v1.x, v1.y, v1.z, v1.w};
        #pragma unroll
        for (int e = 0; e < 8; e++)
            tI[1][e] += s1 * ve[e];
    }

    // ---- epilogue: combine, normalize, fp16 round, store
    #pragma unroll
    for (int r = 0; r < 2; r++) {
        const int i = i0 + r;
        float ci = cw[i], si = sw[i];
        float inv = 1.0f / (nrm[i] + 1e-6f);
        uint32_t ph[4];
        #pragma unroll
        for (int e2 = 0; e2 < 4; e2++) {
            float v0 = (ci * tC[r][e2 * 2 + 0] + si * tS[r][e2 * 2 + 0] + tI[r][e2 * 2 + 0]) * inv;
            float v1 = (ci * tC[r][e2 * 2 + 1] + si * tS[r][e2 * 2 + 1] + tI[r][e2 * 2 + 1]) * inv;
            __half h0 = __float2half(v0);
            __half h1 = __float2half(v1);
            ph[e2] = (uint32_t)__half_as_ushort(h0) |
                     ((uint32_t)__half_as_ushort(h1) << 16);
        }
        size_t base = (size_t)(c * CHUNK + i) * EDIM + h * DDIM + e0;
        *reinterpret_cast<uint4*>(&g_ah[base]) = make_uint4(ph[0], ph[1], ph[2], ph[3]);
    }
}

// ---------------------------------------------------------------------------

static const int SMEM_SUM = (2 * CHUNK * DDIM + 2 * CHUNK) * (int)sizeof(float);
static const int SMEM_OUT = (2 * DDIM * RQT_STRIDE + CHUNK * DDIM + CHUNK * S_STRIDE +
                             2 * DDIM * DDIM + 2 * DDIM + 3 * CHUNK + 4 * CHUNK) * (int)sizeof(float);

extern "C" void kernel_launch(void* const* d_in, const int* in_sizes, int n_in,
                              void* d_out, int out_size) {
    (void)in_sizes; (void)n_in; (void)out_size;
    const float* x    = (const float*)d_in[0];
    const float* Wqkv = (const float*)d_in[1];
    const float* bqkv = (const float*)d_in[2];
    const float* Wout = (const float*)d_in[3];
    const float* bout = (const float*)d_in[4];
    float* out = (float*)d_out;

    __half *qkvh, *xh, *wqh, *woh, *ah;
    cudaGetSymbolAddress((void**)&qkvh, g_qkvh);
    cudaGetSymbolAddress((void**)&xh, g_xh);
    cudaGetSymbolAddress((void**)&wqh, g_wqh);
    cudaGetSymbolAddress((void**)&woh, g_woh);
    cudaGetSymbolAddress((void**)&ah, g_ah);

    cudaFuncSetAttribute(chunk_sum_kernel,
                         cudaFuncAttributeMaxDynamicSharedMemorySize, SMEM_SUM);
    cudaFuncSetAttribute(chunk_out_kernel,
                         cudaFuncAttributeMaxDynamicSharedMemorySize, SMEM_OUT);
    cudaFuncSetAttribute((const void*)mma_gemm_kernel<64, true>,
                         cudaFuncAttributeMaxDynamicSharedMemorySize, GSMEM(64));
    cudaFuncSetAttribute((const void*)mma_gemm_kernel<32, false>,
                         cudaFuncAttributeMaxDynamicSharedMemorySize, GSMEM(32));

    // fp16 conversions: x + Wqkv^T + Wout^T, one launch
    split_all_kernel<<<1024 + 768 + 256, 256>>>(x, Wqkv, Wout);

    // 1) QKV GEMM -> fp16 QKV with fused relu on Q,K cols
    mma_gemm_kernel<64, true><<<dim3(E3 / 128, LSEQ / 64), 256, GSMEM(64)>>>(
        xh, wqh, bqkv, qkvh, E3, EDIM);

    // 2) Chunked cosformer attention (fp16 KV state)
    chunk_sum_kernel<<<dim3(NCH, HEADS), 256, SMEM_SUM>>>();
    scan_kernel<<<128, 256>>>();
    chunk_out_kernel<<<dim3(NCH, HEADS), 256, SMEM_OUT>>>();

    // 3) Output GEMM: fp32 out
    mma_gemm_kernel<32, false><<<dim3(EDIM / 128, LSEQ / 32), 256, GSMEM(32)>>>(
        ah, woh, bout, out, EDIM, EDIM);
}